// round 1
// baseline (speedup 1.0000x reference)
#include <cuda_runtime.h>
#include <stdint.h>
#include <math.h>

// Problem constants
#define CB   32
#define CN   2048
#define CD   512
#define CNS  8
#define MROWS 65536          // CB*CN
#define SROWS 256            // CB*CNS
#define EPS_A 1e-8f
#define LN_EPS 1e-5f
#define ATT_SCALE 0.044194173824159216f  // 512^-0.5

// ---------------- scratch (device globals; no allocation allowed) ----------
__device__ float g_wkv[524288];      // [1024][512] k_w rows then v_w rows
__device__ float g_bkv[1024];
__device__ float g_mean[MROWS];
__device__ float g_rstd[MROWS];
__device__ float g_kv[67108864];     // [65536][1024]: cols 0..511 = k, 512..1023 = v
__device__ float g_slots[131072];    // [256][512]
__device__ float g_q[131072];
__device__ float g_attnT[524288];    // [32][2048][8] softmax over slots (no EPS)
__device__ float g_invsum[256];      // 1/(sum_j sm + N*EPS)
__device__ float g_upart[1048576];   // [8 jsplit][256][512]
__device__ float g_updates[131072];
__device__ float g_gi[393216];       // [256][1536]
__device__ float g_gh[393216];
__device__ float g_s0[131072];
__device__ float g_h1[262144];
__device__ float g_h2[262144];
__device__ float g_h3[131072];

// ---------------- small helpers -------------------------------------------
__device__ __forceinline__ uint32_t f2tf(float f) {
    uint32_t u; asm("cvt.rna.tf32.f32 %0, %1;" : "=r"(u) : "f"(f)); return u;
}
__device__ __forceinline__ float geluf(float x) {
    return 0.5f * x * (1.0f + erff(x * 0.7071067811865476f));
}
__device__ __forceinline__ float sigm(float x) { return 1.0f / (1.0f + expf(-x)); }
__device__ __forceinline__ float warp_sum(float v) {
#pragma unroll
    for (int o = 16; o; o >>= 1) v += __shfl_xor_sync(0xffffffffu, v, o);
    return v;
}
__device__ __forceinline__ void mma_tf32(float c[4], const uint32_t a[4], const uint32_t b[2]) {
    asm volatile(
        "mma.sync.aligned.m16n8k8.row.col.f32.tf32.tf32.f32 "
        "{%0,%1,%2,%3}, {%4,%5,%6,%7}, {%8,%9}, {%0,%1,%2,%3};\n"
        : "+f"(c[0]), "+f"(c[1]), "+f"(c[2]), "+f"(c[3])
        : "r"(a[0]), "r"(a[1]), "r"(a[2]), "r"(a[3]), "r"(b[0]), "r"(b[1]));
}

// ---------------- prologue kernels -----------------------------------------
__global__ void concat_wkv_kernel(const float* __restrict__ kw, const float* __restrict__ vw,
                                  const float* __restrict__ kb, const float* __restrict__ vb) {
    int idx = blockIdx.x * 256 + threadIdx.x;        // grid 2048*256 = 524288
    if (idx < 262144) g_wkv[idx] = kw[idx];
    else              g_wkv[idx] = vw[idx - 262144];
    if (idx < 512)                 g_bkv[idx] = kb[idx];
    else if (idx < 1024)           g_bkv[idx] = vb[idx - 512];
}

__global__ void slot_init_kernel(const float* __restrict__ noise, const float* __restrict__ mu,
                                 const float* __restrict__ ls) {
    int idx = blockIdx.x * 256 + threadIdx.x;        // 131072
    int d = idx & 511;
    g_slots[idx] = mu[d] + expf(ls[d]) * noise[idx];
}

// per-row mean/rstd of inputs (one warp per row)
__global__ void ln_stats_kernel(const float* __restrict__ x) {
    int warp = (blockIdx.x * blockDim.x + threadIdx.x) >> 5;
    int lane = threadIdx.x & 31;
    if (warp >= MROWS) return;
    const float4* xr = (const float4*)(x + (size_t)warp * CD);
    float s = 0.f, s2 = 0.f;
#pragma unroll
    for (int i = 0; i < 4; i++) {
        float4 v = xr[lane + 32 * i];
        s  += v.x + v.y + v.z + v.w;
        s2 += v.x * v.x + v.y * v.y + v.z * v.z + v.w * v.w;
    }
    s = warp_sum(s); s2 = warp_sum(s2);
    if (lane == 0) {
        float m = s * (1.0f / CD);
        float var = s2 * (1.0f / CD) - m * m;
        g_mean[warp] = m;
        g_rstd[warp] = rsqrtf(var + LN_EPS);
    }
}

// full LN of small matrices (one warp per 512-wide row)
__global__ void ln_full_kernel(const float* __restrict__ x, const float* __restrict__ g,
                               const float* __restrict__ b, float* __restrict__ out, int rows) {
    int warp = (blockIdx.x * blockDim.x + threadIdx.x) >> 5;
    int lane = threadIdx.x & 31;
    if (warp >= rows) return;
    const float4* xr = (const float4*)(x + (size_t)warp * CD);
    float4 v[4];
    float s = 0.f, s2 = 0.f;
#pragma unroll
    for (int i = 0; i < 4; i++) {
        v[i] = xr[lane + 32 * i];
        s  += v[i].x + v[i].y + v[i].z + v[i].w;
        s2 += v[i].x * v[i].x + v[i].y * v[i].y + v[i].z * v[i].z + v[i].w * v[i].w;
    }
    s = warp_sum(s); s2 = warp_sum(s2);
    float m = s * (1.0f / CD);
    float var = s2 * (1.0f / CD) - m * m;
    float r = rsqrtf(var + LN_EPS);
    float4* o = (float4*)(out + (size_t)warp * CD);
    const float4* g4p = (const float4*)g;
    const float4* b4p = (const float4*)b;
#pragma unroll
    for (int i = 0; i < 4; i++) {
        float4 g4 = g4p[lane + 32 * i];
        float4 b4 = b4p[lane + 32 * i];
        float4 ov;
        ov.x = (v[i].x - m) * r * g4.x + b4.x;
        ov.y = (v[i].y - m) * r * g4.y + b4.y;
        ov.z = (v[i].z - m) * r * g4.z + b4.z;
        ov.w = (v[i].w - m) * r * g4.w + b4.w;
        o[lane + 32 * i] = ov;
    }
}

// ---------------- tf32 tensor-core GEMM ------------------------------------
// C[M,N] = act( A'[M,K] @ W[N,K]^T + bias )
// A' = LN(A) with (mean,rstd,lng,lnb) when LNA.
// Tiles: BM=BN=128, BK=32; 256 threads = 8 warps (2x4); warp tile 64x32.
template <int ACT, bool LNA>
__global__ __launch_bounds__(256) void gemm_tf32(
    const float* __restrict__ A, int lda,
    const float* __restrict__ mean, const float* __restrict__ rstd,
    const float* __restrict__ lng, const float* __restrict__ lnb,
    const float* __restrict__ W, int ldw,
    const float* __restrict__ bias,
    float* __restrict__ C, int ldc, int K) {
    __shared__ uint32_t As[128][36];
    __shared__ uint32_t Bs[128][36];

    const int m0 = blockIdx.y * 128;
    const int n0 = blockIdx.x * 128;
    const int warp = threadIdx.x >> 5;
    const int lane = threadIdx.x & 31;
    const int gid = lane >> 2;
    const int tig = lane & 3;
    const int mbase = (warp >> 2) * 64;   // wm in {0,1}
    const int nbase = (warp & 3) * 32;    // wn in {0..3}

    float c[4][4][4];
#pragma unroll
    for (int mi = 0; mi < 4; mi++)
#pragma unroll
        for (int ni = 0; ni < 4; ni++)
#pragma unroll
            for (int r = 0; r < 4; r++) c[mi][ni][r] = 0.f;

    for (int kt = 0; kt < K; kt += 32) {
        // load A tile (with optional fused LN) and W tile
#pragma unroll
        for (int it = 0; it < 4; it++) {
            int f = threadIdx.x + it * 256;       // 0..1023
            int r = f >> 3;
            int c4 = (f & 7) << 2;
            {
                int gm = m0 + r;
                float4 x = *(const float4*)(A + (size_t)gm * lda + kt + c4);
                if (LNA) {
                    float mu = mean[gm], rs = rstd[gm];
                    float4 g4 = *(const float4*)(lng + kt + c4);
                    float4 b4 = *(const float4*)(lnb + kt + c4);
                    x.x = (x.x - mu) * rs * g4.x + b4.x;
                    x.y = (x.y - mu) * rs * g4.y + b4.y;
                    x.z = (x.z - mu) * rs * g4.z + b4.z;
                    x.w = (x.w - mu) * rs * g4.w + b4.w;
                }
                As[r][c4 + 0] = f2tf(x.x); As[r][c4 + 1] = f2tf(x.y);
                As[r][c4 + 2] = f2tf(x.z); As[r][c4 + 3] = f2tf(x.w);
            }
            {
                int gn = n0 + r;
                float4 w4 = *(const float4*)(W + (size_t)gn * ldw + kt + c4);
                Bs[r][c4 + 0] = f2tf(w4.x); Bs[r][c4 + 1] = f2tf(w4.y);
                Bs[r][c4 + 2] = f2tf(w4.z); Bs[r][c4 + 3] = f2tf(w4.w);
            }
        }
        __syncthreads();
#pragma unroll
        for (int ks = 0; ks < 4; ks++) {
            uint32_t a[4][4], bf[4][2];
#pragma unroll
            for (int mi = 0; mi < 4; mi++) {
                int row = mbase + mi * 16 + gid;
                int kk = ks * 8 + tig;
                a[mi][0] = As[row][kk];
                a[mi][1] = As[row + 8][kk];
                a[mi][2] = As[row][kk + 4];
                a[mi][3] = As[row + 8][kk + 4];
            }
#pragma unroll
            for (int ni = 0; ni < 4; ni++) {
                int col = nbase + ni * 8 + gid;
                int kk = ks * 8 + tig;
                bf[ni][0] = Bs[col][kk];
                bf[ni][1] = Bs[col][kk + 4];
            }
#pragma unroll
            for (int mi = 0; mi < 4; mi++)
#pragma unroll
                for (int ni = 0; ni < 4; ni++) mma_tf32(c[mi][ni], a[mi], bf[ni]);
        }
        __syncthreads();
    }

    // epilogue
#pragma unroll
    for (int mi = 0; mi < 4; mi++) {
        int r0 = m0 + mbase + mi * 16 + gid;
#pragma unroll
        for (int ni = 0; ni < 4; ni++) {
            int col = n0 + nbase + ni * 8 + tig * 2;
            float bv0 = __ldg(bias + col), bv1 = __ldg(bias + col + 1);
            float v00 = c[mi][ni][0] + bv0, v01 = c[mi][ni][1] + bv1;
            float v10 = c[mi][ni][2] + bv0, v11 = c[mi][ni][3] + bv1;
            if (ACT == 1) { v00 = geluf(v00); v01 = geluf(v01); v10 = geluf(v10); v11 = geluf(v11); }
            *(float2*)(C + (size_t)r0 * ldc + col)       = make_float2(v00, v01);
            *(float2*)(C + (size_t)(r0 + 8) * ldc + col) = make_float2(v10, v11);
        }
    }
}

// ---------------- attention kernels ----------------------------------------
// dots + softmax over the 8 slots, stored transposed: g_attnT[b][j][slot]
__global__ void dots_softmax_kernel() {
    const int bx = blockIdx.x;   // token chunk (64 tokens)
    const int by = blockIdx.y;   // batch
    __shared__ float qs[4096];   // 8 slots x 512
    {
        const float4* qg = (const float4*)(g_q + (size_t)by * 4096);
        float4* qs4 = (float4*)qs;
        for (int f = threadIdx.x; f < 1024; f += 256) qs4[f] = qg[f];
    }
    __syncthreads();
    const int warp = threadIdx.x >> 5;
    const int lane = threadIdx.x & 31;
#pragma unroll 1
    for (int tt = 0; tt < 8; tt++) {
        int j = bx * 64 + warp * 8 + tt;
        const float4* krow = (const float4*)(g_kv + (size_t)(by * CN + j) * 1024);
        float acc[8];
#pragma unroll
        for (int s = 0; s < 8; s++) acc[s] = 0.f;
#pragma unroll
        for (int cc = 0; cc < 4; cc++) {
            float4 k4 = krow[cc * 32 + lane];
#pragma unroll
            for (int s = 0; s < 8; s++) {
                float4 q4 = ((const float4*)qs)[s * 128 + cc * 32 + lane];
                acc[s] += k4.x * q4.x + k4.y * q4.y + k4.z * q4.z + k4.w * q4.w;
            }
        }
#pragma unroll
        for (int o = 16; o; o >>= 1)
#pragma unroll
            for (int s = 0; s < 8; s++) acc[s] += __shfl_xor_sync(0xffffffffu, acc[s], o);
        float mx = acc[0];
#pragma unroll
        for (int s = 1; s < 8; s++) mx = fmaxf(mx, acc[s]);
        float e[8], sum = 0.f;
#pragma unroll
        for (int s = 0; s < 8; s++) { e[s] = expf((acc[s] - mx) * ATT_SCALE); sum += e[s]; }
        float inv = 1.0f / sum;
        float val = 0.f;
#pragma unroll
        for (int s = 0; s < 8; s++) if (lane == s) val = e[s] * inv;
        if (lane < 8) g_attnT[(size_t)(by * CN + j) * 8 + lane] = val;
    }
}

// per (b,slot) token sum -> inverse denominator
__global__ void attn_sums_kernel() {
    const int b = blockIdx.x;
    const int t = threadIdx.x;                       // 256
    __shared__ float s[256];
    const float* base = g_attnT + (size_t)b * CN * 8;
    float acc = 0.f;
    for (int e = t; e < CN * 8; e += 256) acc += base[e];   // i = t&7 fixed
    s[t] = acc;
    __syncthreads();
    for (int off = 128; off >= 8; off >>= 1) {
        if (t < off) s[t] += s[t + off];
        __syncthreads();
    }
    if (t < 8) g_invsum[b * 8 + t] = 1.0f / (s[t] + (float)CN * EPS_A);
}

// partial updates: j split in 8 chunks of 256 tokens
__global__ void upd_partial_kernel() {
    const int dx = blockIdx.x;   // 0..3 (128 cols each)
    const int b  = blockIdx.y;   // batch
    const int jz = blockIdx.z;   // 0..7
    const int t  = threadIdx.x;  // 128
    __shared__ float atts[2048]; // 256 tokens x 8 (EPS pre-added)
    {
        const float4* ap = (const float4*)(g_attnT + (size_t)(b * CN + jz * 256) * 8);
        float4* as4 = (float4*)atts;
        for (int f = t; f < 512; f += 128) {
            float4 v = ap[f];
            v.x += EPS_A; v.y += EPS_A; v.z += EPS_A; v.w += EPS_A;
            as4[f] = v;
        }
    }
    __syncthreads();
    const int d = dx * 128 + t;
    const float* vp = g_kv + (size_t)(b * CN + jz * 256) * 1024 + 512 + d;
    float acc[8];
#pragma unroll
    for (int s = 0; s < 8; s++) acc[s] = 0.f;
#pragma unroll 4
    for (int jj = 0; jj < 256; jj++) {
        float vv = vp[(size_t)jj * 1024];
#pragma unroll
        for (int s = 0; s < 8; s++) acc[s] += vv * atts[jj * 8 + s];
    }
#pragma unroll
    for (int s = 0; s < 8; s++)
        g_upart[(size_t)jz * 131072 + (size_t)(b * 8 + s) * 512 + d] = acc[s];
}

__global__ void upd_reduce_kernel(float* __restrict__ out2) {
    int idx = blockIdx.x * 256 + threadIdx.x;        // 131072
    int row = idx >> 9;
    float tot = 0.f;
#pragma unroll
    for (int jz = 0; jz < 8; jz++) tot += g_upart[(size_t)jz * 131072 + idx];
    tot *= g_invsum[row];
    g_updates[idx] = tot;
    if (out2) out2[idx] = tot;
}

__global__ void gru_elem_kernel() {
    int idx = blockIdx.x * 256 + threadIdx.x;        // 131072
    int r = idx >> 9, d = idx & 511;
    const float* gir = g_gi + (size_t)r * 1536;
    const float* ghr = g_gh + (size_t)r * 1536;
    float i_r = gir[d], i_z = gir[d + 512], i_n = gir[d + 1024];
    float h_r = ghr[d], h_z = ghr[d + 512], h_n = ghr[d + 1024];
    float rg = sigm(i_r + h_r);
    float z  = sigm(i_z + h_z);
    float nn = tanhf(i_n + rg * h_n);
    float h  = g_slots[idx];
    float h_new = (1.0f - z) * nn + z * h;
    g_slots[idx] = g_updates[idx] + h_new;
}

// ---------------- launcher --------------------------------------------------
#define SYM(p, s) do { void* _v = nullptr; cudaGetSymbolAddress(&_v, s); (p) = (float*)_v; } while (0)

extern "C" void kernel_launch(void* const* d_in, const int* in_sizes, int n_in,
                              void* d_out, int out_size) {
    (void)in_sizes; (void)n_in; (void)out_size;
    const float* inputs         = (const float*)d_in[0];
    const float* slot_noise     = (const float*)d_in[1];
    const float* slots_mu       = (const float*)d_in[2];
    const float* slots_logsigma = (const float*)d_in[3];
    const float* k_w  = (const float*)d_in[4];
    const float* k_b  = (const float*)d_in[5];
    const float* v_w  = (const float*)d_in[6];
    const float* v_b  = (const float*)d_in[7];
    const float* gru_w_ih = (const float*)d_in[8];
    const float* gru_w_hh = (const float*)d_in[9];
    const float* gru_b_ih = (const float*)d_in[10];
    const float* gru_b_hh = (const float*)d_in[11];
    const float* ln_in_g = (const float*)d_in[12];
    const float* ln_in_b = (const float*)d_in[13];
    const float* ln_slots_g = (const float*)d_in[14];
    const float* ln_slots_b = (const float*)d_in[15];
    const float* ln_pre_g = (const float*)d_in[16];
    const float* ln_pre_b = (const float*)d_in[17];
    const float* mlp1_w = (const float*)d_in[18];
    const float* mlp1_b = (const float*)d_in[19];
    const float* mlp2_w = (const float*)d_in[20];
    const float* mlp2_b = (const float*)d_in[21];
    const float* mlp3_w = (const float*)d_in[22];
    const float* mlp3_b = (const float*)d_in[23];
    const float* mlp4_w = (const float*)d_in[24];
    const float* mlp4_b = (const float*)d_in[25];
    float* out = (float*)d_out;

    float *p_wkv, *p_bkv, *p_kv, *p_mean, *p_rstd, *p_slots, *p_q, *p_upd;
    float *p_gi, *p_gh, *p_s0, *p_h1, *p_h2, *p_h3;
    SYM(p_wkv, g_wkv);   SYM(p_bkv, g_bkv);  SYM(p_kv, g_kv);
    SYM(p_mean, g_mean); SYM(p_rstd, g_rstd);
    SYM(p_slots, g_slots); SYM(p_q, g_q); SYM(p_upd, g_updates);
    SYM(p_gi, g_gi); SYM(p_gh, g_gh); SYM(p_s0, g_s0);
    SYM(p_h1, g_h1); SYM(p_h2, g_h2); SYM(p_h3, g_h3);

    concat_wkv_kernel<<<2048, 256>>>(k_w, v_w, k_b, v_b);
    slot_init_kernel<<<512, 256>>>(slot_noise, slots_mu, slots_logsigma);
    ln_stats_kernel<<<8192, 256>>>(inputs);

    // k,v projection with fused input-LN: [65536,512] x [1024,512]^T -> g_kv
    gemm_tf32<0, true><<<dim3(8, 512), 256>>>(inputs, 512, p_mean, p_rstd,
                                              ln_in_g, ln_in_b,
                                              p_wkv, 512, p_bkv, p_kv, 1024, 512);

    for (int it = 0; it < 3; it++) {
        ln_full_kernel<<<32, 256>>>(p_slots, ln_slots_g, ln_slots_b, p_q, SROWS);
        dots_softmax_kernel<<<dim3(32, 32), 256>>>();
        attn_sums_kernel<<<32, 256>>>();
        upd_partial_kernel<<<dim3(4, 32, 8), 128>>>();
        upd_reduce_kernel<<<512, 256>>>((it == 2) ? out : nullptr);
        gemm_tf32<0, false><<<dim3(12, 2), 256>>>(p_upd, 512, nullptr, nullptr, nullptr, nullptr,
                                                  gru_w_ih, 512, gru_b_ih, p_gi, 1536, 512);
        gemm_tf32<0, false><<<dim3(12, 2), 256>>>(p_slots, 512, nullptr, nullptr, nullptr, nullptr,
                                                  gru_w_hh, 512, gru_b_hh, p_gh, 1536, 512);
        gru_elem_kernel<<<512, 256>>>();
    }

    ln_full_kernel<<<32, 256>>>(p_slots, ln_pre_g, ln_pre_b, p_s0, SROWS);
    gemm_tf32<1, false><<<dim3(8, 2), 256>>>(p_s0, 512, nullptr, nullptr, nullptr, nullptr,
                                             mlp1_w, 512, mlp1_b, p_h1, 1024, 512);
    gemm_tf32<1, false><<<dim3(8, 2), 256>>>(p_h1, 1024, nullptr, nullptr, nullptr, nullptr,
                                             mlp2_w, 1024, mlp2_b, p_h2, 1024, 1024);
    gemm_tf32<1, false><<<dim3(4, 2), 256>>>(p_h2, 1024, nullptr, nullptr, nullptr, nullptr,
                                             mlp3_w, 1024, mlp3_b, p_h3, 512, 1024);
    gemm_tf32<0, false><<<dim3(2, 2), 256>>>(p_h3, 512, nullptr, nullptr, nullptr, nullptr,
                                             mlp4_w, 512, mlp4_b, out + 131072, 256, 512);
}

// round 3
// speedup vs baseline: 1.1940x; 1.1940x over previous
#include <cuda_runtime.h>
#include <stdint.h>
#include <math.h>

// Problem constants
#define CB   32
#define CN   2048
#define CD   512
#define CNS  8
#define MROWS 65536          // CB*CN
#define SROWS 256            // CB*CNS
#define EPS_A 1e-8f
#define LN_EPS 1e-5f
#define ATT_SCALE 0.044194173824159216f  // 512^-0.5

// ---------------- scratch (device globals; no allocation allowed) ----------
__device__ float g_wkv[524288];      // [1024][512] k_w rows then v_w rows (tf32-rounded)
__device__ float g_bkv[1024];
__device__ float g_xln[33554432];    // [65536][512] tf32(LN(inputs))
__device__ float g_kv[67108864];     // [65536][1024]: cols 0..511 = k, 512..1023 = v
__device__ float g_slots[131072];    // [256][512]
__device__ float g_q[131072];
__device__ float g_attnT[524288];    // [32][2048][8] softmax over slots (no EPS)
__device__ float g_invsum[256];      // 1/(sum_j sm + N*EPS)
__device__ float g_upart[1048576];   // [8 jsplit][256][512]
__device__ float g_updates[131072];
__device__ float g_gi[393216];       // [256][1536]
__device__ float g_gh[393216];
__device__ float g_s0[131072];
__device__ float g_h1[262144];
__device__ float g_h2[262144];
__device__ float g_h3[131072];

// ---------------- small helpers -------------------------------------------
__device__ __forceinline__ uint32_t f2tf(float f) {
    uint32_t u; asm("cvt.rna.tf32.f32 %0, %1;" : "=r"(u) : "f"(f)); return u;
}
__device__ __forceinline__ float geluf(float x) {
    return 0.5f * x * (1.0f + erff(x * 0.7071067811865476f));
}
__device__ __forceinline__ float sigm(float x) { return 1.0f / (1.0f + expf(-x)); }
__device__ __forceinline__ float warp_sum(float v) {
#pragma unroll
    for (int o = 16; o; o >>= 1) v += __shfl_xor_sync(0xffffffffu, v, o);
    return v;
}
__device__ __forceinline__ void mma_tf32(float c[4], const uint32_t a[4], const uint32_t b[2]) {
    asm volatile(
        "mma.sync.aligned.m16n8k8.row.col.f32.tf32.tf32.f32 "
        "{%0,%1,%2,%3}, {%4,%5,%6,%7}, {%8,%9}, {%0,%1,%2,%3};\n"
        : "+f"(c[0]), "+f"(c[1]), "+f"(c[2]), "+f"(c[3])
        : "r"(a[0]), "r"(a[1]), "r"(a[2]), "r"(a[3]), "r"(b[0]), "r"(b[1]));
}
__device__ __forceinline__ uint32_t smem_u32(const void* p) {
    uint32_t a;
    asm("{ .reg .u64 t; cvta.to.shared.u64 t, %1; cvt.u32.u64 %0, t; }" : "=r"(a) : "l"(p));
    return a;
}
__device__ __forceinline__ void cpa16(uint32_t dst, const void* src) {
    asm volatile("cp.async.cg.shared.global [%0], [%1], 16;" :: "r"(dst), "l"(src));
}
#define CPA_COMMIT() asm volatile("cp.async.commit_group;" ::: "memory")
#define CPA_WAIT1()  asm volatile("cp.async.wait_group 1;" ::: "memory")
#define CPA_WAIT0()  asm volatile("cp.async.wait_group 0;" ::: "memory")

// ---------------- prologue kernels -----------------------------------------
__global__ void concat_wkv_kernel(const float* __restrict__ kw, const float* __restrict__ vw,
                                  const float* __restrict__ kb, const float* __restrict__ vb) {
    int idx = blockIdx.x * 256 + threadIdx.x;        // 524288
    float w = (idx < 262144) ? kw[idx] : vw[idx - 262144];
    g_wkv[idx] = __uint_as_float(f2tf(w));           // tf32-rounded
    if (idx < 512)                 g_bkv[idx] = kb[idx];
    else if (idx < 1024)           g_bkv[idx] = vb[idx - 512];
}

__global__ void slot_init_kernel(const float* __restrict__ noise, const float* __restrict__ mu,
                                 const float* __restrict__ ls) {
    int idx = blockIdx.x * 256 + threadIdx.x;        // 131072
    int d = idx & 511;
    g_slots[idx] = mu[d] + expf(ls[d]) * noise[idx];
}

// LN(inputs) -> tf32-rounded g_xln  (one warp per 512-wide row)
__global__ void ln_writeX_kernel(const float* __restrict__ x, const float* __restrict__ g,
                                 const float* __restrict__ b) {
    int warp = (blockIdx.x * blockDim.x + threadIdx.x) >> 5;
    int lane = threadIdx.x & 31;
    if (warp >= MROWS) return;
    const float4* xr = (const float4*)(x + (size_t)warp * CD);
    float4 v[4];
    float s = 0.f, s2 = 0.f;
#pragma unroll
    for (int i = 0; i < 4; i++) {
        v[i] = xr[lane + 32 * i];
        s  += v[i].x + v[i].y + v[i].z + v[i].w;
        s2 += v[i].x * v[i].x + v[i].y * v[i].y + v[i].z * v[i].z + v[i].w * v[i].w;
    }
    s = warp_sum(s); s2 = warp_sum(s2);
    float m = s * (1.0f / CD);
    float var = s2 * (1.0f / CD) - m * m;
    float r = rsqrtf(var + LN_EPS);
    float4* o = (float4*)(g_xln + (size_t)warp * CD);
    const float4* g4p = (const float4*)g;
    const float4* b4p = (const float4*)b;
#pragma unroll
    for (int i = 0; i < 4; i++) {
        float4 g4 = g4p[lane + 32 * i];
        float4 b4 = b4p[lane + 32 * i];
        float4 ov;
        ov.x = __uint_as_float(f2tf((v[i].x - m) * r * g4.x + b4.x));
        ov.y = __uint_as_float(f2tf((v[i].y - m) * r * g4.y + b4.y));
        ov.z = __uint_as_float(f2tf((v[i].z - m) * r * g4.z + b4.z));
        ov.w = __uint_as_float(f2tf((v[i].w - m) * r * g4.w + b4.w));
        o[lane + 32 * i] = ov;
    }
}

// full LN of small matrices (one warp per 512-wide row)
__global__ void ln_full_kernel(const float* __restrict__ x, const float* __restrict__ g,
                               const float* __restrict__ b, float* __restrict__ out, int rows) {
    int warp = (blockIdx.x * blockDim.x + threadIdx.x) >> 5;
    int lane = threadIdx.x & 31;
    if (warp >= rows) return;
    const float4* xr = (const float4*)(x + (size_t)warp * CD);
    float4 v[4];
    float s = 0.f, s2 = 0.f;
#pragma unroll
    for (int i = 0; i < 4; i++) {
        v[i] = xr[lane + 32 * i];
        s  += v[i].x + v[i].y + v[i].z + v[i].w;
        s2 += v[i].x * v[i].x + v[i].y * v[i].y + v[i].z * v[i].z + v[i].w * v[i].w;
    }
    s = warp_sum(s); s2 = warp_sum(s2);
    float m = s * (1.0f / CD);
    float var = s2 * (1.0f / CD) - m * m;
    float r = rsqrtf(var + LN_EPS);
    float4* o = (float4*)(out + (size_t)warp * CD);
    const float4* g4p = (const float4*)g;
    const float4* b4p = (const float4*)b;
#pragma unroll
    for (int i = 0; i < 4; i++) {
        float4 g4 = g4p[lane + 32 * i];
        float4 b4 = b4p[lane + 32 * i];
        float4 ov;
        ov.x = (v[i].x - m) * r * g4.x + b4.x;
        ov.y = (v[i].y - m) * r * g4.y + b4.y;
        ov.z = (v[i].z - m) * r * g4.z + b4.z;
        ov.w = (v[i].w - m) * r * g4.w + b4.w;
        o[lane + 32 * i] = ov;
    }
}

// ---------------- pipelined kv GEMM (cp.async, 3 stages) --------------------
// C[65536,1024] = g_xln[65536,512] @ g_wkv[1024,512]^T + g_bkv
// 128x128 block, BK=32, 8 warps (2x4), warp tile 64x32.
// smem: 3 stages x (A 128x36 + B 128x36) floats = 110592 B.
#define KVP_STRIDE 36
#define KVP_TILE   (128 * KVP_STRIDE)          // floats per tile
#define KVP_SMEM_BYTES (3 * 2 * KVP_TILE * 4)  // 110592

__global__ __launch_bounds__(256) void kv_gemm_pipe() {
    extern __shared__ float sm[];
    float* As = sm;                    // [3][128][36]
    float* Bs = sm + 3 * KVP_TILE;     // [3][128][36]
    const uint32_t sa = smem_u32(As);
    const uint32_t sb = smem_u32(Bs);

    const int tid = threadIdx.x;
    const int n0 = blockIdx.x * 128;
    const int m0 = blockIdx.y * 128;
    const int warp = tid >> 5;
    const int lane = tid & 31;
    const int gid = lane >> 2;
    const int tig = lane & 3;
    const int mbase = (warp >> 2) * 64;
    const int nbase = (warp & 3) * 32;

    // per-thread copy coordinates: 4 chunks of 16B per tile per matrix
    const int cr = tid >> 3;           // base row step: rows cr, cr+32, cr+64, cr+96
    const int cc = (tid & 7) * 4;      // float col

    float c[4][4][4];
#pragma unroll
    for (int mi = 0; mi < 4; mi++)
#pragma unroll
        for (int ni = 0; ni < 4; ni++)
#pragma unroll
            for (int r = 0; r < 4; r++) c[mi][ni][r] = 0.f;

    // tile issue helper (macro to keep regs low)
#define KVP_ISSUE(KT, ST)                                                          \
    do {                                                                           \
        uint32_t a_s = sa + (ST) * (KVP_TILE * 4);                                 \
        uint32_t b_s = sb + (ST) * (KVP_TILE * 4);                                 \
        _Pragma("unroll")                                                          \
        for (int i = 0; i < 4; i++) {                                              \
            int r = cr + i * 32;                                                   \
            cpa16(a_s + (r * KVP_STRIDE + cc) * 4,                                 \
                  g_xln + (size_t)(m0 + r) * 512 + (KT) * 32 + cc);                \
            cpa16(b_s + (r * KVP_STRIDE + cc) * 4,                                 \
                  g_wkv + (size_t)(n0 + r) * 512 + (KT) * 32 + cc);                \
        }                                                                          \
        CPA_COMMIT();                                                              \
    } while (0)

    KVP_ISSUE(0, 0);
    KVP_ISSUE(1, 1);

#pragma unroll 1
    for (int kt = 0; kt < 16; kt++) {
        if (kt < 15) CPA_WAIT1(); else CPA_WAIT0();
        __syncthreads();
        if (kt + 2 < 16) KVP_ISSUE(kt + 2, (kt + 2) % 3);

        const float* At = As + (kt % 3) * KVP_TILE;
        const float* Bt = Bs + (kt % 3) * KVP_TILE;
#pragma unroll
        for (int ks = 0; ks < 4; ks++) {
            uint32_t a[4][4], bf[4][2];
            int kk = ks * 8 + tig;
#pragma unroll
            for (int mi = 0; mi < 4; mi++) {
                const float* ap = At + (mbase + mi * 16 + gid) * KVP_STRIDE;
                a[mi][0] = __float_as_uint(ap[kk]);
                a[mi][1] = __float_as_uint(ap[8 * KVP_STRIDE + kk]);
                a[mi][2] = __float_as_uint(ap[kk + 4]);
                a[mi][3] = __float_as_uint(ap[8 * KVP_STRIDE + kk + 4]);
            }
#pragma unroll
            for (int ni = 0; ni < 4; ni++) {
                const float* bp = Bt + (nbase + ni * 8 + gid) * KVP_STRIDE;
                bf[ni][0] = __float_as_uint(bp[kk]);
                bf[ni][1] = __float_as_uint(bp[kk + 4]);
            }
#pragma unroll
            for (int mi = 0; mi < 4; mi++)
#pragma unroll
                for (int ni = 0; ni < 4; ni++) mma_tf32(c[mi][ni], a[mi], bf[ni]);
        }
        __syncthreads();
    }
#undef KVP_ISSUE

    // epilogue: bias add, write to g_kv
#pragma unroll
    for (int mi = 0; mi < 4; mi++) {
        int r0 = m0 + mbase + mi * 16 + gid;
#pragma unroll
        for (int ni = 0; ni < 4; ni++) {
            int col = n0 + nbase + ni * 8 + tig * 2;
            float bv0 = __ldg(g_bkv + col), bv1 = __ldg(g_bkv + col + 1);
            *(float2*)(g_kv + (size_t)r0 * 1024 + col) =
                make_float2(c[mi][ni][0] + bv0, c[mi][ni][1] + bv1);
            *(float2*)(g_kv + (size_t)(r0 + 8) * 1024 + col) =
                make_float2(c[mi][ni][2] + bv0, c[mi][ni][3] + bv1);
        }
    }
}

// ---------------- tf32 mma.sync GEMM (GRU / MLP; small M) -------------------
template <int ACT, bool LNA>
__global__ __launch_bounds__(256) void gemm_tf32(
    const float* __restrict__ A, int lda,
    const float* __restrict__ mean, const float* __restrict__ rstd,
    const float* __restrict__ lng, const float* __restrict__ lnb,
    const float* __restrict__ W, int ldw,
    const float* __restrict__ bias,
    float* __restrict__ C, int ldc, int K) {
    __shared__ uint32_t As[128][36];
    __shared__ uint32_t Bs[128][36];

    const int m0 = blockIdx.y * 128;
    const int n0 = blockIdx.x * 128;
    const int warp = threadIdx.x >> 5;
    const int lane = threadIdx.x & 31;
    const int gid = lane >> 2;
    const int tig = lane & 3;
    const int mbase = (warp >> 2) * 64;
    const int nbase = (warp & 3) * 32;

    float c[4][4][4];
#pragma unroll
    for (int mi = 0; mi < 4; mi++)
#pragma unroll
        for (int ni = 0; ni < 4; ni++)
#pragma unroll
            for (int r = 0; r < 4; r++) c[mi][ni][r] = 0.f;

    for (int kt = 0; kt < K; kt += 32) {
#pragma unroll
        for (int it = 0; it < 4; it++) {
            int f = threadIdx.x + it * 256;
            int r = f >> 3;
            int c4 = (f & 7) << 2;
            {
                int gm = m0 + r;
                float4 x = *(const float4*)(A + (size_t)gm * lda + kt + c4);
                if (LNA) {
                    float mu = mean[gm], rs = rstd[gm];
                    float4 g4 = *(const float4*)(lng + kt + c4);
                    float4 b4 = *(const float4*)(lnb + kt + c4);
                    x.x = (x.x - mu) * rs * g4.x + b4.x;
                    x.y = (x.y - mu) * rs * g4.y + b4.y;
                    x.z = (x.z - mu) * rs * g4.z + b4.z;
                    x.w = (x.w - mu) * rs * g4.w + b4.w;
                }
                As[r][c4 + 0] = f2tf(x.x); As[r][c4 + 1] = f2tf(x.y);
                As[r][c4 + 2] = f2tf(x.z); As[r][c4 + 3] = f2tf(x.w);
            }
            {
                int gn = n0 + r;
                float4 w4 = *(const float4*)(W + (size_t)gn * ldw + kt + c4);
                Bs[r][c4 + 0] = f2tf(w4.x); Bs[r][c4 + 1] = f2tf(w4.y);
                Bs[r][c4 + 2] = f2tf(w4.z); Bs[r][c4 + 3] = f2tf(w4.w);
            }
        }
        __syncthreads();
#pragma unroll
        for (int ks = 0; ks < 4; ks++) {
            uint32_t a[4][4], bf[4][2];
#pragma unroll
            for (int mi = 0; mi < 4; mi++) {
                int row = mbase + mi * 16 + gid;
                int kk = ks * 8 + tig;
                a[mi][0] = As[row][kk];
                a[mi][1] = As[row + 8][kk];
                a[mi][2] = As[row][kk + 4];
                a[mi][3] = As[row + 8][kk + 4];
            }
#pragma unroll
            for (int ni = 0; ni < 4; ni++) {
                int col = nbase + ni * 8 + gid;
                int kk = ks * 8 + tig;
                bf[ni][0] = Bs[col][kk];
                bf[ni][1] = Bs[col][kk + 4];
            }
#pragma unroll
            for (int mi = 0; mi < 4; mi++)
#pragma unroll
                for (int ni = 0; ni < 4; ni++) mma_tf32(c[mi][ni], a[mi], bf[ni]);
        }
        __syncthreads();
    }

#pragma unroll
    for (int mi = 0; mi < 4; mi++) {
        int r0 = m0 + mbase + mi * 16 + gid;
#pragma unroll
        for (int ni = 0; ni < 4; ni++) {
            int col = n0 + nbase + ni * 8 + tig * 2;
            float bv0 = __ldg(bias + col), bv1 = __ldg(bias + col + 1);
            float v00 = c[mi][ni][0] + bv0, v01 = c[mi][ni][1] + bv1;
            float v10 = c[mi][ni][2] + bv0, v11 = c[mi][ni][3] + bv1;
            if (ACT == 1) { v00 = geluf(v00); v01 = geluf(v01); v10 = geluf(v10); v11 = geluf(v11); }
            *(float2*)(C + (size_t)r0 * ldc + col)       = make_float2(v00, v01);
            *(float2*)(C + (size_t)(r0 + 8) * ldc + col) = make_float2(v10, v11);
        }
    }
}

// ---------------- attention kernels ----------------------------------------
__global__ void dots_softmax_kernel() {
    const int bx = blockIdx.x;   // token chunk (64 tokens)
    const int by = blockIdx.y;   // batch
    __shared__ float qs[4096];   // 8 slots x 512
    {
        const float4* qg = (const float4*)(g_q + (size_t)by * 4096);
        float4* qs4 = (float4*)qs;
        for (int f = threadIdx.x; f < 1024; f += 256) qs4[f] = qg[f];
    }
    __syncthreads();
    const int warp = threadIdx.x >> 5;
    const int lane = threadIdx.x & 31;
#pragma unroll 1
    for (int tt = 0; tt < 8; tt++) {
        int j = bx * 64 + warp * 8 + tt;
        const float4* krow = (const float4*)(g_kv + (size_t)(by * CN + j) * 1024);
        float acc[8];
#pragma unroll
        for (int s = 0; s < 8; s++) acc[s] = 0.f;
#pragma unroll
        for (int cc = 0; cc < 4; cc++) {
            float4 k4 = krow[cc * 32 + lane];
#pragma unroll
            for (int s = 0; s < 8; s++) {
                float4 q4 = ((const float4*)qs)[s * 128 + cc * 32 + lane];
                acc[s] += k4.x * q4.x + k4.y * q4.y + k4.z * q4.z + k4.w * q4.w;
            }
        }
#pragma unroll
        for (int o = 16; o; o >>= 1)
#pragma unroll
            for (int s = 0; s < 8; s++) acc[s] += __shfl_xor_sync(0xffffffffu, acc[s], o);
        float mx = acc[0];
#pragma unroll
        for (int s = 1; s < 8; s++) mx = fmaxf(mx, acc[s]);
        float e[8], sum = 0.f;
#pragma unroll
        for (int s = 0; s < 8; s++) { e[s] = expf((acc[s] - mx) * ATT_SCALE); sum += e[s]; }
        float inv = 1.0f / sum;
        float val = 0.f;
#pragma unroll
        for (int s = 0; s < 8; s++) if (lane == s) val = e[s] * inv;
        if (lane < 8) g_attnT[(size_t)(by * CN + j) * 8 + lane] = val;
    }
}

__global__ void attn_sums_kernel() {
    const int b = blockIdx.x;
    const int t = threadIdx.x;
    __shared__ float s[256];
    const float* base = g_attnT + (size_t)b * CN * 8;
    float acc = 0.f;
    for (int e = t; e < CN * 8; e += 256) acc += base[e];
    s[t] = acc;
    __syncthreads();
    for (int off = 128; off >= 8; off >>= 1) {
        if (t < off) s[t] += s[t + off];
        __syncthreads();
    }
    if (t < 8) g_invsum[b * 8 + t] = 1.0f / (s[t] + (float)CN * EPS_A);
}

__global__ void upd_partial_kernel() {
    const int dx = blockIdx.x;
    const int b  = blockIdx.y;
    const int jz = blockIdx.z;
    const int t  = threadIdx.x;
    __shared__ float atts[2048];
    {
        const float4* ap = (const float4*)(g_attnT + (size_t)(b * CN + jz * 256) * 8);
        float4* as4 = (float4*)atts;
        for (int f = t; f < 512; f += 128) {
            float4 v = ap[f];
            v.x += EPS_A; v.y += EPS_A; v.z += EPS_A; v.w += EPS_A;
            as4[f] = v;
        }
    }
    __syncthreads();
    const int d = dx * 128 + t;
    const float* vp = g_kv + (size_t)(b * CN + jz * 256) * 1024 + 512 + d;
    float acc[8];
#pragma unroll
    for (int s = 0; s < 8; s++) acc[s] = 0.f;
#pragma unroll 4
    for (int jj = 0; jj < 256; jj++) {
        float vv = vp[(size_t)jj * 1024];
#pragma unroll
        for (int s = 0; s < 8; s++) acc[s] += vv * atts[jj * 8 + s];
    }
#pragma unroll
    for (int s = 0; s < 8; s++)
        g_upart[(size_t)jz * 131072 + (size_t)(b * 8 + s) * 512 + d] = acc[s];
}

__global__ void upd_reduce_kernel(float* __restrict__ out2) {
    int idx = blockIdx.x * 256 + threadIdx.x;
    int row = idx >> 9;
    float tot = 0.f;
#pragma unroll
    for (int jz = 0; jz < 8; jz++) tot += g_upart[(size_t)jz * 131072 + idx];
    tot *= g_invsum[row];
    g_updates[idx] = tot;
    if (out2) out2[idx] = tot;
}

__global__ void gru_elem_kernel() {
    int idx = blockIdx.x * 256 + threadIdx.x;
    int r = idx >> 9, d = idx & 511;
    const float* gir = g_gi + (size_t)r * 1536;
    const float* ghr = g_gh + (size_t)r * 1536;
    float i_r = gir[d], i_z = gir[d + 512], i_n = gir[d + 1024];
    float h_r = ghr[d], h_z = ghr[d + 512], h_n = ghr[d + 1024];
    float rg = sigm(i_r + h_r);
    float z  = sigm(i_z + h_z);
    float nn = tanhf(i_n + rg * h_n);
    float h  = g_slots[idx];
    float h_new = (1.0f - z) * nn + z * h;
    g_slots[idx] = g_updates[idx] + h_new;
}

// ---------------- launcher --------------------------------------------------
#define SYM(p, s) do { void* _v = nullptr; cudaGetSymbolAddress(&_v, s); (p) = (float*)_v; } while (0)

extern "C" void kernel_launch(void* const* d_in, const int* in_sizes, int n_in,
                              void* d_out, int out_size) {
    (void)in_sizes; (void)n_in; (void)out_size;
    const float* inputs         = (const float*)d_in[0];
    const float* slot_noise     = (const float*)d_in[1];
    const float* slots_mu       = (const float*)d_in[2];
    const float* slots_logsigma = (const float*)d_in[3];
    const float* k_w  = (const float*)d_in[4];
    const float* k_b  = (const float*)d_in[5];
    const float* v_w  = (const float*)d_in[6];
    const float* v_b  = (const float*)d_in[7];
    const float* gru_w_ih = (const float*)d_in[8];
    const float* gru_w_hh = (const float*)d_in[9];
    const float* gru_b_ih = (const float*)d_in[10];
    const float* gru_b_hh = (const float*)d_in[11];
    const float* ln_in_g = (const float*)d_in[12];
    const float* ln_in_b = (const float*)d_in[13];
    const float* ln_slots_g = (const float*)d_in[14];
    const float* ln_slots_b = (const float*)d_in[15];
    const float* ln_pre_g = (const float*)d_in[16];
    const float* ln_pre_b = (const float*)d_in[17];
    const float* mlp1_w = (const float*)d_in[18];
    const float* mlp1_b = (const float*)d_in[19];
    const float* mlp2_w = (const float*)d_in[20];
    const float* mlp2_b = (const float*)d_in[21];
    const float* mlp3_w = (const float*)d_in[22];
    const float* mlp3_b = (const float*)d_in[23];
    const float* mlp4_w = (const float*)d_in[24];
    const float* mlp4_b = (const float*)d_in[25];
    float* out = (float*)d_out;

    float *p_slots, *p_q, *p_upd, *p_gi, *p_gh, *p_s0, *p_h1, *p_h2, *p_h3;
    SYM(p_slots, g_slots); SYM(p_q, g_q); SYM(p_upd, g_updates);
    SYM(p_gi, g_gi); SYM(p_gh, g_gh); SYM(p_s0, g_s0);
    SYM(p_h1, g_h1); SYM(p_h2, g_h2); SYM(p_h3, g_h3);

    cudaFuncSetAttribute(kv_gemm_pipe, cudaFuncAttributeMaxDynamicSharedMemorySize, KVP_SMEM_BYTES);

    concat_wkv_kernel<<<2048, 256>>>(k_w, v_w, k_b, v_b);
    slot_init_kernel<<<512, 256>>>(slot_noise, slots_mu, slots_logsigma);
    ln_writeX_kernel<<<8192, 256>>>(inputs, ln_in_g, ln_in_b);

    // k,v projection: pipelined cp.async tf32 GEMM on precomputed LN'd inputs
    kv_gemm_pipe<<<dim3(8, 512), 256, KVP_SMEM_BYTES>>>();

    for (int it = 0; it < 3; it++) {
        ln_full_kernel<<<32, 256>>>(p_slots, ln_slots_g, ln_slots_b, p_q, SROWS);
        dots_softmax_kernel<<<dim3(32, 32), 256>>>();
        attn_sums_kernel<<<32, 256>>>();
        upd_partial_kernel<<<dim3(4, 32, 8), 128>>>();
        upd_reduce_kernel<<<512, 256>>>((it == 2) ? out : nullptr);
        gemm_tf32<0, false><<<dim3(12, 2), 256>>>(p_upd, 512, nullptr, nullptr, nullptr, nullptr,
                                                  gru_w_ih, 512, gru_b_ih, p_gi, 1536, 512);
        gemm_tf32<0, false><<<dim3(12, 2), 256>>>(p_slots, 512, nullptr, nullptr, nullptr, nullptr,
                                                  gru_w_hh, 512, gru_b_hh, p_gh, 1536, 512);
        gru_elem_kernel<<<512, 256>>>();
    }

    ln_full_kernel<<<32, 256>>>(p_slots, ln_pre_g, ln_pre_b, p_s0, SROWS);
    gemm_tf32<1, false><<<dim3(8, 2), 256>>>(p_s0, 512, nullptr, nullptr, nullptr, nullptr,
                                             mlp1_w, 512, mlp1_b, p_h1, 1024, 512);
    gemm_tf32<1, false><<<dim3(8, 2), 256>>>(p_h1, 1024, nullptr, nullptr, nullptr, nullptr,
                                             mlp2_w, 1024, mlp2_b, p_h2, 1024, 1024);
    gemm_tf32<1, false><<<dim3(4, 2), 256>>>(p_h2, 1024, nullptr, nullptr, nullptr, nullptr,
                                             mlp3_w, 1024, mlp3_b, p_h3, 512, 1024);
    gemm_tf32<0, false><<<dim3(2, 2), 256>>>(p_h3, 512, nullptr, nullptr, nullptr, nullptr,
                                             mlp4_w, 512, mlp4_b, out + 131072, 256, 512);
}

// round 4
// speedup vs baseline: 1.4086x; 1.1797x over previous
#include <cuda_runtime.h>
#include <stdint.h>
#include <math.h>

// Problem constants
#define CB   32
#define CN   2048
#define CD   512
#define CNS  8
#define MROWS 65536          // CB*CN
#define SROWS 256            // CB*CNS
#define EPS_A 1e-8f
#define LN_EPS 1e-5f
#define ATT_SCALE 0.044194173824159216f  // 512^-0.5

// ---------------- scratch (device globals; no allocation allowed) ----------
__device__ float g_wkv[524288];      // [1024][512] k_w rows then v_w rows (tf32-rounded)
__device__ float g_bkv[1024];
__device__ float g_xln[33554432];    // [65536][512] tf32(LN(inputs))
__device__ float g_kv[67108864];     // [65536][1024]: cols 0..511 = k, 512..1023 = v
__device__ float g_slots[131072];    // [256][512]
__device__ float g_q[131072];
__device__ float g_attnT[524288];    // [32][2048][8] softmax over slots (no EPS)
__device__ float g_invsum[256];      // 1/(sum_j sm + N*EPS)
__device__ float g_upart[1048576];   // [8 jsplit][256][512]
__device__ float g_updates[131072];
__device__ float g_gi[393216];       // [256][1536]
__device__ float g_gh[393216];
__device__ float g_s0[131072];
__device__ float g_h1[262144];
__device__ float g_h2[262144];
__device__ float g_h3[131072];

// ---------------- small helpers -------------------------------------------
__device__ __forceinline__ uint32_t f2tf(float f) {
    uint32_t u; asm("cvt.rna.tf32.f32 %0, %1;" : "=r"(u) : "f"(f)); return u;
}
__device__ __forceinline__ float geluf(float x) {
    return 0.5f * x * (1.0f + erff(x * 0.7071067811865476f));
}
__device__ __forceinline__ float sigm(float x) { return 1.0f / (1.0f + expf(-x)); }
__device__ __forceinline__ float warp_sum(float v) {
#pragma unroll
    for (int o = 16; o; o >>= 1) v += __shfl_xor_sync(0xffffffffu, v, o);
    return v;
}
__device__ __forceinline__ void mma_tf32(float c[4], const uint32_t a[4], const uint32_t b[2]) {
    asm volatile(
        "mma.sync.aligned.m16n8k8.row.col.f32.tf32.tf32.f32 "
        "{%0,%1,%2,%3}, {%4,%5,%6,%7}, {%8,%9}, {%0,%1,%2,%3};\n"
        : "+f"(c[0]), "+f"(c[1]), "+f"(c[2]), "+f"(c[3])
        : "r"(a[0]), "r"(a[1]), "r"(a[2]), "r"(a[3]), "r"(b[0]), "r"(b[1]));
}
__device__ __forceinline__ uint32_t smem_u32(const void* p) {
    uint32_t a;
    asm("{ .reg .u64 t; cvta.to.shared.u64 t, %1; cvt.u32.u64 %0, t; }" : "=r"(a) : "l"(p));
    return a;
}
__device__ __forceinline__ void cpa16(uint32_t dst, const void* src) {
    asm volatile("cp.async.cg.shared.global [%0], [%1], 16;" :: "r"(dst), "l"(src));
}
#define CPA_COMMIT() asm volatile("cp.async.commit_group;" ::: "memory")
#define CPA_WAIT1()  asm volatile("cp.async.wait_group 1;" ::: "memory")
#define CPA_WAIT0()  asm volatile("cp.async.wait_group 0;" ::: "memory")
#define LDSM4(r, a) \
    asm volatile("ldmatrix.sync.aligned.m8n8.x4.shared.b16 {%0,%1,%2,%3}, [%4];" \
        : "=r"((r)[0]), "=r"((r)[1]), "=r"((r)[2]), "=r"((r)[3]) : "r"(a))
#define LDSM2(r, a) \
    asm volatile("ldmatrix.sync.aligned.m8n8.x2.shared.b16 {%0,%1}, [%2];" \
        : "=r"((r)[0]), "=r"((r)[1]) : "r"(a))

// ---------------- prologue kernels -----------------------------------------
__global__ void concat_wkv_kernel(const float* __restrict__ kw, const float* __restrict__ vw,
                                  const float* __restrict__ kb, const float* __restrict__ vb) {
    int idx = blockIdx.x * 256 + threadIdx.x;        // 524288
    float w = (idx < 262144) ? kw[idx] : vw[idx - 262144];
    g_wkv[idx] = __uint_as_float(f2tf(w));           // tf32-rounded
    if (idx < 512)                 g_bkv[idx] = kb[idx];
    else if (idx < 1024)           g_bkv[idx] = vb[idx - 512];
}

__global__ void slot_init_kernel(const float* __restrict__ noise, const float* __restrict__ mu,
                                 const float* __restrict__ ls) {
    int idx = blockIdx.x * 256 + threadIdx.x;        // 131072
    int d = idx & 511;
    g_slots[idx] = mu[d] + expf(ls[d]) * noise[idx];
}

// LN(inputs) -> tf32-rounded g_xln  (one warp per 512-wide row)
__global__ void ln_writeX_kernel(const float* __restrict__ x, const float* __restrict__ g,
                                 const float* __restrict__ b) {
    int warp = (blockIdx.x * blockDim.x + threadIdx.x) >> 5;
    int lane = threadIdx.x & 31;
    if (warp >= MROWS) return;
    const float4* xr = (const float4*)(x + (size_t)warp * CD);
    float4 v[4];
    float s = 0.f, s2 = 0.f;
#pragma unroll
    for (int i = 0; i < 4; i++) {
        v[i] = xr[lane + 32 * i];
        s  += v[i].x + v[i].y + v[i].z + v[i].w;
        s2 += v[i].x * v[i].x + v[i].y * v[i].y + v[i].z * v[i].z + v[i].w * v[i].w;
    }
    s = warp_sum(s); s2 = warp_sum(s2);
    float m = s * (1.0f / CD);
    float var = s2 * (1.0f / CD) - m * m;
    float r = rsqrtf(var + LN_EPS);
    float4* o = (float4*)(g_xln + (size_t)warp * CD);
    const float4* g4p = (const float4*)g;
    const float4* b4p = (const float4*)b;
#pragma unroll
    for (int i = 0; i < 4; i++) {
        float4 g4 = g4p[lane + 32 * i];
        float4 b4 = b4p[lane + 32 * i];
        float4 ov;
        ov.x = __uint_as_float(f2tf((v[i].x - m) * r * g4.x + b4.x));
        ov.y = __uint_as_float(f2tf((v[i].y - m) * r * g4.y + b4.y));
        ov.z = __uint_as_float(f2tf((v[i].z - m) * r * g4.z + b4.z));
        ov.w = __uint_as_float(f2tf((v[i].w - m) * r * g4.w + b4.w));
        o[lane + 32 * i] = ov;
    }
}

// full LN of small matrices (one warp per 512-wide row)
__global__ void ln_full_kernel(const float* __restrict__ x, const float* __restrict__ g,
                               const float* __restrict__ b, float* __restrict__ out, int rows) {
    int warp = (blockIdx.x * blockDim.x + threadIdx.x) >> 5;
    int lane = threadIdx.x & 31;
    if (warp >= rows) return;
    const float4* xr = (const float4*)(x + (size_t)warp * CD);
    float4 v[4];
    float s = 0.f, s2 = 0.f;
#pragma unroll
    for (int i = 0; i < 4; i++) {
        v[i] = xr[lane + 32 * i];
        s  += v[i].x + v[i].y + v[i].z + v[i].w;
        s2 += v[i].x * v[i].x + v[i].y * v[i].y + v[i].z * v[i].z + v[i].w * v[i].w;
    }
    s = warp_sum(s); s2 = warp_sum(s2);
    float m = s * (1.0f / CD);
    float var = s2 * (1.0f / CD) - m * m;
    float r = rsqrtf(var + LN_EPS);
    float4* o = (float4*)(out + (size_t)warp * CD);
    const float4* g4p = (const float4*)g;
    const float4* b4p = (const float4*)b;
#pragma unroll
    for (int i = 0; i < 4; i++) {
        float4 g4 = g4p[lane + 32 * i];
        float4 b4 = b4p[lane + 32 * i];
        float4 ov;
        ov.x = (v[i].x - m) * r * g4.x + b4.x;
        ov.y = (v[i].y - m) * r * g4.y + b4.y;
        ov.z = (v[i].z - m) * r * g4.z + b4.z;
        ov.w = (v[i].w - m) * r * g4.w + b4.w;
        o[lane + 32 * i] = ov;
    }
}

// ---------------- pipelined kv GEMM (cp.async + ldmatrix) -------------------
// C[65536,1024] = g_xln[65536,512] @ g_wkv[1024,512]^T + g_bkv
// 128x128 block, BK=32, 4 warps (2x2), warp tile 64x64, ldmatrix-fed MMAs.
#define KVP_STRIDE 36
#define KVP_TILE   (128 * KVP_STRIDE)          // floats per tile
#define KVP_TILE_B (KVP_TILE * 4)              // bytes per tile
#define KVP_SMEM_BYTES (3 * 2 * KVP_TILE_B)    // 110592

__global__ void __launch_bounds__(128, 2) kv_gemm_pipe() {
    extern __shared__ float sm[];
    float* As = sm;                    // [3][128][36]
    float* Bs = sm + 3 * KVP_TILE;     // [3][128][36]
    const uint32_t sa = smem_u32(As);
    const uint32_t sb = smem_u32(Bs);

    const int tid = threadIdx.x;
    const int n0 = blockIdx.x * 128;
    const int m0 = blockIdx.y * 128;
    const int warp = tid >> 5;
    const int lane = tid & 31;
    const int gid = lane >> 2;
    const int tig = lane & 3;
    const int mbase = (warp >> 1) * 64;   // 2x2 warp grid
    const int nbase = (warp & 1) * 64;

    // ldmatrix lane address components
    // A x4: m = lane>>3; matrices (rows 0-7, k0), (rows 8-15, k0), (rows 0-7, k+4), (rows 8-15, k+4)
    const int a_row = ((lane >> 3) & 1) * 8 + (lane & 7);
    const int a_k4  = (lane >> 4) * 4;
    // B x2: lanes 0-7 -> (n rows, k0), lanes 8-15 -> (n rows, k+4)
    const int b_row = lane & 7;
    const int b_k4  = ((lane >> 3) & 1) * 4;
    const uint32_t a_lane_off = (uint32_t)(((mbase + a_row) * KVP_STRIDE + a_k4) * 4);
    const uint32_t b_lane_off = (uint32_t)(((nbase + b_row) * KVP_STRIDE + b_k4) * 4);

    // copy coordinates: 8 chunks of 16B per matrix per stage per thread
    const int cr = tid >> 3;           // 0..15, rows cr + i*16
    const int cc = (tid & 7) * 4;      // float col

    float c[4][8][4];
#pragma unroll
    for (int mi = 0; mi < 4; mi++)
#pragma unroll
        for (int ni = 0; ni < 8; ni++)
#pragma unroll
            for (int r = 0; r < 4; r++) c[mi][ni][r] = 0.f;

#define KVP_ISSUE(KT, ST)                                                          \
    do {                                                                           \
        uint32_t a_s = sa + (ST) * KVP_TILE_B;                                     \
        uint32_t b_s = sb + (ST) * KVP_TILE_B;                                     \
        _Pragma("unroll")                                                          \
        for (int i = 0; i < 8; i++) {                                              \
            int r = cr + i * 16;                                                   \
            cpa16(a_s + (r * KVP_STRIDE + cc) * 4,                                 \
                  g_xln + (size_t)(m0 + r) * 512 + (KT) * 32 + cc);                \
            cpa16(b_s + (r * KVP_STRIDE + cc) * 4,                                 \
                  g_wkv + (size_t)(n0 + r) * 512 + (KT) * 32 + cc);                \
        }                                                                          \
        CPA_COMMIT();                                                              \
    } while (0)

    KVP_ISSUE(0, 0);
    KVP_ISSUE(1, 1);

#pragma unroll 1
    for (int kt = 0; kt < 16; kt++) {
        if (kt < 15) CPA_WAIT1(); else CPA_WAIT0();
        __syncthreads();
        if (kt + 2 < 16) KVP_ISSUE(kt + 2, (kt + 2) % 3);

        const uint32_t At = sa + (kt % 3) * KVP_TILE_B + a_lane_off;
        const uint32_t Bt = sb + (kt % 3) * KVP_TILE_B + b_lane_off;
#pragma unroll
        for (int ks = 0; ks < 4; ks++) {
            uint32_t a[4][4], bf[8][2];
#pragma unroll
            for (int mi = 0; mi < 4; mi++)
                LDSM4(a[mi], At + mi * (16 * KVP_STRIDE * 4) + ks * 32);
#pragma unroll
            for (int ni = 0; ni < 8; ni++)
                LDSM2(bf[ni], Bt + ni * (8 * KVP_STRIDE * 4) + ks * 32);
#pragma unroll
            for (int mi = 0; mi < 4; mi++)
#pragma unroll
                for (int ni = 0; ni < 8; ni++) mma_tf32(c[mi][ni], a[mi], bf[ni]);
        }
        __syncthreads();
    }
#undef KVP_ISSUE

    // epilogue: bias add, write to g_kv
#pragma unroll
    for (int mi = 0; mi < 4; mi++) {
        int r0 = m0 + mbase + mi * 16 + gid;
#pragma unroll
        for (int ni = 0; ni < 8; ni++) {
            int col = n0 + nbase + ni * 8 + tig * 2;
            float bv0 = __ldg(g_bkv + col), bv1 = __ldg(g_bkv + col + 1);
            *(float2*)(g_kv + (size_t)r0 * 1024 + col) =
                make_float2(c[mi][ni][0] + bv0, c[mi][ni][1] + bv1);
            *(float2*)(g_kv + (size_t)(r0 + 8) * 1024 + col) =
                make_float2(c[mi][ni][2] + bv0, c[mi][ni][3] + bv1);
        }
    }
}

// ---------------- tf32 mma.sync GEMM core (GRU / MLP; small M) ---------------
template <int ACT>
__device__ __forceinline__ void gemm_core(
    const float* __restrict__ A, int lda,
    const float* __restrict__ W, int ldw,
    const float* __restrict__ bias,
    float* __restrict__ C, int ldc, int K, int m0, int n0) {
    __shared__ uint32_t As[128][36];
    __shared__ uint32_t Bs[128][36];

    const int warp = threadIdx.x >> 5;
    const int lane = threadIdx.x & 31;
    const int gid = lane >> 2;
    const int tig = lane & 3;
    const int mbase = (warp >> 2) * 64;
    const int nbase = (warp & 3) * 32;

    float c[4][4][4];
#pragma unroll
    for (int mi = 0; mi < 4; mi++)
#pragma unroll
        for (int ni = 0; ni < 4; ni++)
#pragma unroll
            for (int r = 0; r < 4; r++) c[mi][ni][r] = 0.f;

    for (int kt = 0; kt < K; kt += 32) {
#pragma unroll
        for (int it = 0; it < 4; it++) {
            int f = threadIdx.x + it * 256;
            int r = f >> 3;
            int c4 = (f & 7) << 2;
            {
                float4 x = *(const float4*)(A + (size_t)(m0 + r) * lda + kt + c4);
                As[r][c4 + 0] = f2tf(x.x); As[r][c4 + 1] = f2tf(x.y);
                As[r][c4 + 2] = f2tf(x.z); As[r][c4 + 3] = f2tf(x.w);
            }
            {
                float4 w4 = *(const float4*)(W + (size_t)(n0 + r) * ldw + kt + c4);
                Bs[r][c4 + 0] = f2tf(w4.x); Bs[r][c4 + 1] = f2tf(w4.y);
                Bs[r][c4 + 2] = f2tf(w4.z); Bs[r][c4 + 3] = f2tf(w4.w);
            }
        }
        __syncthreads();
#pragma unroll
        for (int ks = 0; ks < 4; ks++) {
            uint32_t a[4][4], bf[4][2];
            int kk = ks * 8 + tig;
#pragma unroll
            for (int mi = 0; mi < 4; mi++) {
                int row = mbase + mi * 16 + gid;
                a[mi][0] = As[row][kk];
                a[mi][1] = As[row + 8][kk];
                a[mi][2] = As[row][kk + 4];
                a[mi][3] = As[row + 8][kk + 4];
            }
#pragma unroll
            for (int ni = 0; ni < 4; ni++) {
                int col = nbase + ni * 8 + gid;
                bf[ni][0] = Bs[col][kk];
                bf[ni][1] = Bs[col][kk + 4];
            }
#pragma unroll
            for (int mi = 0; mi < 4; mi++)
#pragma unroll
                for (int ni = 0; ni < 4; ni++) mma_tf32(c[mi][ni], a[mi], bf[ni]);
        }
        __syncthreads();
    }

#pragma unroll
    for (int mi = 0; mi < 4; mi++) {
        int r0 = m0 + mbase + mi * 16 + gid;
#pragma unroll
        for (int ni = 0; ni < 4; ni++) {
            int col = n0 + nbase + ni * 8 + tig * 2;
            float bv0 = __ldg(bias + col), bv1 = __ldg(bias + col + 1);
            float v00 = c[mi][ni][0] + bv0, v01 = c[mi][ni][1] + bv1;
            float v10 = c[mi][ni][2] + bv0, v11 = c[mi][ni][3] + bv1;
            if (ACT == 1) { v00 = geluf(v00); v01 = geluf(v01); v10 = geluf(v10); v11 = geluf(v11); }
            *(float2*)(C + (size_t)r0 * ldc + col)       = make_float2(v00, v01);
            *(float2*)(C + (size_t)(r0 + 8) * ldc + col) = make_float2(v10, v11);
        }
    }
}

template <int ACT>
__global__ __launch_bounds__(256) void gemm_tf32(
    const float* __restrict__ A, int lda,
    const float* __restrict__ W, int ldw,
    const float* __restrict__ bias,
    float* __restrict__ C, int ldc, int K) {
    gemm_core<ACT>(A, lda, W, ldw, bias, C, ldc, K, blockIdx.y * 128, blockIdx.x * 128);
}

// merged GRU pair: z=0 -> gi = updates @ w_ih^T + b_ih ; z=1 -> gh = slots @ w_hh^T + b_hh
__global__ __launch_bounds__(256) void gru_gemm_dual(
    const float* __restrict__ w_ih, const float* __restrict__ w_hh,
    const float* __restrict__ b_ih, const float* __restrict__ b_hh) {
    const float* A = (blockIdx.z == 0) ? g_updates : g_slots;
    const float* W = (blockIdx.z == 0) ? w_ih : w_hh;
    const float* bias = (blockIdx.z == 0) ? b_ih : b_hh;
    float* C = (blockIdx.z == 0) ? g_gi : g_gh;
    gemm_core<0>(A, 512, W, 512, bias, C, 1536, 512, blockIdx.y * 128, blockIdx.x * 128);
}

// ---------------- attention kernels ----------------------------------------
__global__ void dots_softmax_kernel() {
    const int bx = blockIdx.x;   // token chunk (64 tokens)
    const int by = blockIdx.y;   // batch
    __shared__ float qs[4096];   // 8 slots x 512
    {
        const float4* qg = (const float4*)(g_q + (size_t)by * 4096);
        float4* qs4 = (float4*)qs;
        for (int f = threadIdx.x; f < 1024; f += 256) qs4[f] = qg[f];
    }
    __syncthreads();
    const int warp = threadIdx.x >> 5;
    const int lane = threadIdx.x & 31;
#pragma unroll 1
    for (int tt = 0; tt < 8; tt++) {
        int j = bx * 64 + warp * 8 + tt;
        const float4* krow = (const float4*)(g_kv + (size_t)(by * CN + j) * 1024);
        float acc[8];
#pragma unroll
        for (int s = 0; s < 8; s++) acc[s] = 0.f;
#pragma unroll
        for (int cc = 0; cc < 4; cc++) {
            float4 k4 = krow[cc * 32 + lane];
#pragma unroll
            for (int s = 0; s < 8; s++) {
                float4 q4 = ((const float4*)qs)[s * 128 + cc * 32 + lane];
                acc[s] += k4.x * q4.x + k4.y * q4.y + k4.z * q4.z + k4.w * q4.w;
            }
        }
#pragma unroll
        for (int o = 16; o; o >>= 1)
#pragma unroll
            for (int s = 0; s < 8; s++) acc[s] += __shfl_xor_sync(0xffffffffu, acc[s], o);
        float mx = acc[0];
#pragma unroll
        for (int s = 1; s < 8; s++) mx = fmaxf(mx, acc[s]);
        float e[8], sum = 0.f;
#pragma unroll
        for (int s = 0; s < 8; s++) { e[s] = expf((acc[s] - mx) * ATT_SCALE); sum += e[s]; }
        float inv = 1.0f / sum;
        float val = 0.f;
#pragma unroll
        for (int s = 0; s < 8; s++) if (lane == s) val = e[s] * inv;
        if (lane < 8) g_attnT[(size_t)(by * CN + j) * 8 + lane] = val;
    }
}

__global__ void attn_sums_kernel() {
    const int b = blockIdx.x;
    const int t = threadIdx.x;
    __shared__ float s[256];
    const float* base = g_attnT + (size_t)b * CN * 8;
    float acc = 0.f;
    for (int e = t; e < CN * 8; e += 256) acc += base[e];
    s[t] = acc;
    __syncthreads();
    for (int off = 128; off >= 8; off >>= 1) {
        if (t < off) s[t] += s[t + off];
        __syncthreads();
    }
    if (t < 8) g_invsum[b * 8 + t] = 1.0f / (s[t] + (float)CN * EPS_A);
}

__global__ void upd_partial_kernel() {
    const int dx = blockIdx.x;   // 0..1 (256 cols each)
    const int b  = blockIdx.y;   // batch
    const int jz = blockIdx.z;   // 0..7
    const int t  = threadIdx.x;  // 256
    __shared__ float atts[2048]; // 256 tokens x 8 (EPS pre-added)
    {
        const float4* ap = (const float4*)(g_attnT + (size_t)(b * CN + jz * 256) * 8);
        float4* as4 = (float4*)atts;
        for (int f = t; f < 512; f += 256) {
            float4 v = ap[f];
            v.x += EPS_A; v.y += EPS_A; v.z += EPS_A; v.w += EPS_A;
            as4[f] = v;
        }
    }
    __syncthreads();
    const int d = dx * 256 + t;
    const float* vp = g_kv + (size_t)(b * CN + jz * 256) * 1024 + 512 + d;
    float acc[8];
#pragma unroll
    for (int s = 0; s < 8; s++) acc[s] = 0.f;
#pragma unroll 8
    for (int jj = 0; jj < 256; jj++) {
        float vv = vp[(size_t)jj * 1024];
#pragma unroll
        for (int s = 0; s < 8; s++) acc[s] += vv * atts[jj * 8 + s];
    }
#pragma unroll
    for (int s = 0; s < 8; s++)
        g_upart[(size_t)jz * 131072 + (size_t)(b * 8 + s) * 512 + d] = acc[s];
}

__global__ void upd_reduce_kernel(float* __restrict__ out2) {
    int idx = blockIdx.x * 256 + threadIdx.x;
    int row = idx >> 9;
    float tot = 0.f;
#pragma unroll
    for (int jz = 0; jz < 8; jz++) tot += g_upart[(size_t)jz * 131072 + idx];
    tot *= g_invsum[row];
    g_updates[idx] = tot;
    if (out2) out2[idx] = tot;
}

__global__ void gru_elem_kernel() {
    int idx = blockIdx.x * 256 + threadIdx.x;
    int r = idx >> 9, d = idx & 511;
    const float* gir = g_gi + (size_t)r * 1536;
    const float* ghr = g_gh + (size_t)r * 1536;
    float i_r = gir[d], i_z = gir[d + 512], i_n = gir[d + 1024];
    float h_r = ghr[d], h_z = ghr[d + 512], h_n = ghr[d + 1024];
    float rg = sigm(i_r + h_r);
    float z  = sigm(i_z + h_z);
    float nn = tanhf(i_n + rg * h_n);
    float h  = g_slots[idx];
    float h_new = (1.0f - z) * nn + z * h;
    g_slots[idx] = g_updates[idx] + h_new;
}

// ---------------- launcher --------------------------------------------------
#define SYM(p, s) do { void* _v = nullptr; cudaGetSymbolAddress(&_v, s); (p) = (float*)_v; } while (0)

extern "C" void kernel_launch(void* const* d_in, const int* in_sizes, int n_in,
                              void* d_out, int out_size) {
    (void)in_sizes; (void)n_in; (void)out_size;
    const float* inputs         = (const float*)d_in[0];
    const float* slot_noise     = (const float*)d_in[1];
    const float* slots_mu       = (const float*)d_in[2];
    const float* slots_logsigma = (const float*)d_in[3];
    const float* k_w  = (const float*)d_in[4];
    const float* k_b  = (const float*)d_in[5];
    const float* v_w  = (const float*)d_in[6];
    const float* v_b  = (const float*)d_in[7];
    const float* gru_w_ih = (const float*)d_in[8];
    const float* gru_w_hh = (const float*)d_in[9];
    const float* gru_b_ih = (const float*)d_in[10];
    const float* gru_b_hh = (const float*)d_in[11];
    const float* ln_in_g = (const float*)d_in[12];
    const float* ln_in_b = (const float*)d_in[13];
    const float* ln_slots_g = (const float*)d_in[14];
    const float* ln_slots_b = (const float*)d_in[15];
    const float* ln_pre_g = (const float*)d_in[16];
    const float* ln_pre_b = (const float*)d_in[17];
    const float* mlp1_w = (const float*)d_in[18];
    const float* mlp1_b = (const float*)d_in[19];
    const float* mlp2_w = (const float*)d_in[20];
    const float* mlp2_b = (const float*)d_in[21];
    const float* mlp3_w = (const float*)d_in[22];
    const float* mlp3_b = (const float*)d_in[23];
    const float* mlp4_w = (const float*)d_in[24];
    const float* mlp4_b = (const float*)d_in[25];
    float* out = (float*)d_out;

    float *p_slots, *p_q, *p_s0, *p_h1, *p_h2, *p_h3;
    SYM(p_slots, g_slots); SYM(p_q, g_q); SYM(p_s0, g_s0);
    SYM(p_h1, g_h1); SYM(p_h2, g_h2); SYM(p_h3, g_h3);

    cudaFuncSetAttribute(kv_gemm_pipe, cudaFuncAttributeMaxDynamicSharedMemorySize, KVP_SMEM_BYTES);

    concat_wkv_kernel<<<2048, 256>>>(k_w, v_w, k_b, v_b);
    slot_init_kernel<<<512, 256>>>(slot_noise, slots_mu, slots_logsigma);
    ln_writeX_kernel<<<8192, 256>>>(inputs, ln_in_g, ln_in_b);

    // k,v projection: pipelined cp.async + ldmatrix tf32 GEMM
    kv_gemm_pipe<<<dim3(8, 512), 128, KVP_SMEM_BYTES>>>();

    for (int it = 0; it < 3; it++) {
        ln_full_kernel<<<32, 256>>>(p_slots, ln_slots_g, ln_slots_b, p_q, SROWS);
        dots_softmax_kernel<<<dim3(32, 32), 256>>>();
        attn_sums_kernel<<<32, 256>>>();
        upd_partial_kernel<<<dim3(2, 32, 8), 256>>>();
        upd_reduce_kernel<<<512, 256>>>((it == 2) ? out : nullptr);
        gru_gemm_dual<<<dim3(12, 2, 2), 256>>>(gru_w_ih, gru_w_hh, gru_b_ih, gru_b_hh);
        gru_elem_kernel<<<512, 256>>>();
    }

    ln_full_kernel<<<32, 256>>>(p_slots, ln_pre_g, ln_pre_b, p_s0, SROWS);
    gemm_tf32<1><<<dim3(8, 2), 256>>>(p_s0, 512, mlp1_w, 512, mlp1_b, p_h1, 1024, 512);
    gemm_tf32<1><<<dim3(8, 2), 256>>>(p_h1, 1024, mlp2_w, 1024, mlp2_b, p_h2, 1024, 1024);
    gemm_tf32<1><<<dim3(4, 2), 256>>>(p_h2, 1024, mlp3_w, 1024, mlp3_b, p_h3, 512, 1024);
    gemm_tf32<0><<<dim3(2, 2), 256>>>(p_h3, 512, mlp4_w, 512, mlp4_b, out + 131072, 256, 512);
}

// round 5
// speedup vs baseline: 1.7021x; 1.2084x over previous
#include <cuda_runtime.h>
#include <stdint.h>
#include <math.h>

// Problem constants
#define CB   32
#define CN   2048
#define CD   512
#define CNS  8
#define MROWS 65536          // CB*CN
#define SROWS 256            // CB*CNS
#define EPS_A 1e-8f
#define LN_EPS 1e-5f
#define ATT_SCALE 0.044194173824159216f  // 512^-0.5

// ---------------- scratch (device globals; no allocation allowed) ----------
__device__ float g_xln[33554432];    // [65536][512] LN(inputs), fp32
__device__ float g_kwT[262144];      // kw transposed: g_kwT[d][e] = kw[e][d]
__device__ float g_slots[131072];    // [256][512]
__device__ float g_q[131072];        // LN(slots)
__device__ float g_qk[131072];       // q contracted with kw
__device__ float g_qkb[256];         // q . k_b
__device__ float g_paw[1048576];     // [8 chunk][256 rows=b*8+s][512] partial sm-weighted x
__device__ float g_pssum[2048];      // [8 chunk][256] partial softmax sums
__device__ float g_pxsum[131072];    // [8 chunk][32 b][512] partial x sums
__device__ float g_aw[131072];       // attention-weighted x (normalized)
__device__ float g_updates[131072];
__device__ float g_gi[393216];       // [256][1536]
__device__ float g_gh[393216];
__device__ float g_s0[131072];
__device__ float g_h1[262144];
__device__ float g_h2[262144];
__device__ float g_h3[131072];

// ---------------- small helpers -------------------------------------------
__device__ __forceinline__ uint32_t f2tf(float f) {
    uint32_t u; asm("cvt.rna.tf32.f32 %0, %1;" : "=r"(u) : "f"(f)); return u;
}
__device__ __forceinline__ float geluf(float x) {
    return 0.5f * x * (1.0f + erff(x * 0.7071067811865476f));
}
__device__ __forceinline__ float sigm(float x) { return 1.0f / (1.0f + expf(-x)); }
__device__ __forceinline__ float warp_sum(float v) {
#pragma unroll
    for (int o = 16; o; o >>= 1) v += __shfl_xor_sync(0xffffffffu, v, o);
    return v;
}
__device__ __forceinline__ void mma_tf32(float c[4], const uint32_t a[4], const uint32_t b[2]) {
    asm volatile(
        "mma.sync.aligned.m16n8k8.row.col.f32.tf32.tf32.f32 "
        "{%0,%1,%2,%3}, {%4,%5,%6,%7}, {%8,%9}, {%0,%1,%2,%3};\n"
        : "+f"(c[0]), "+f"(c[1]), "+f"(c[2]), "+f"(c[3])
        : "r"(a[0]), "r"(a[1]), "r"(a[2]), "r"(a[3]), "r"(b[0]), "r"(b[1]));
}
__device__ __forceinline__ uint32_t smem_u32(const void* p) {
    uint32_t a;
    asm("{ .reg .u64 t; cvta.to.shared.u64 t, %1; cvt.u32.u64 %0, t; }" : "=r"(a) : "l"(p));
    return a;
}
__device__ __forceinline__ void cpa16(uint32_t dst, const void* src) {
    asm volatile("cp.async.cg.shared.global [%0], [%1], 16;" :: "r"(dst), "l"(src));
}
#define CPA_COMMIT() asm volatile("cp.async.commit_group;" ::: "memory")
#define CPA_WAIT1()  asm volatile("cp.async.wait_group 1;" ::: "memory")
#define CPA_WAIT0()  asm volatile("cp.async.wait_group 0;" ::: "memory")

// ---------------- prologue kernels -----------------------------------------
__global__ void slot_init_kernel(const float* __restrict__ noise, const float* __restrict__ mu,
                                 const float* __restrict__ ls) {
    int idx = blockIdx.x * 256 + threadIdx.x;        // 131072
    int d = idx & 511;
    g_slots[idx] = mu[d] + expf(ls[d]) * noise[idx];
}

// kw transpose: g_kwT[d][e] = kw[e][d]
__global__ void transpose_kw_kernel(const float* __restrict__ kw) {
    __shared__ float t[32][33];
    int bx = blockIdx.x * 32, by = blockIdx.y * 32;
    int tx = threadIdx.x, ty = threadIdx.y;     // 32 x 8
#pragma unroll
    for (int i = 0; i < 32; i += 8)
        t[ty + i][tx] = kw[(size_t)(by + ty + i) * 512 + bx + tx];
    __syncthreads();
#pragma unroll
    for (int i = 0; i < 32; i += 8)
        g_kwT[(size_t)(bx + ty + i) * 512 + by + tx] = t[tx][ty + i];
}

// LN(inputs) -> g_xln (full fp32, one warp per row)
__global__ void ln_writeX_kernel(const float* __restrict__ x, const float* __restrict__ g,
                                 const float* __restrict__ b) {
    int warp = (blockIdx.x * blockDim.x + threadIdx.x) >> 5;
    int lane = threadIdx.x & 31;
    if (warp >= MROWS) return;
    const float4* xr = (const float4*)(x + (size_t)warp * CD);
    float4 v[4];
    float s = 0.f, s2 = 0.f;
#pragma unroll
    for (int i = 0; i < 4; i++) {
        v[i] = xr[lane + 32 * i];
        s  += v[i].x + v[i].y + v[i].z + v[i].w;
        s2 += v[i].x * v[i].x + v[i].y * v[i].y + v[i].z * v[i].z + v[i].w * v[i].w;
    }
    s = warp_sum(s); s2 = warp_sum(s2);
    float m = s * (1.0f / CD);
    float var = s2 * (1.0f / CD) - m * m;
    float r = rsqrtf(var + LN_EPS);
    float4* o = (float4*)(g_xln + (size_t)warp * CD);
    const float4* g4p = (const float4*)g;
    const float4* b4p = (const float4*)b;
#pragma unroll
    for (int i = 0; i < 4; i++) {
        float4 g4 = g4p[lane + 32 * i];
        float4 b4 = b4p[lane + 32 * i];
        float4 ov;
        ov.x = (v[i].x - m) * r * g4.x + b4.x;
        ov.y = (v[i].y - m) * r * g4.y + b4.y;
        ov.z = (v[i].z - m) * r * g4.z + b4.z;
        ov.w = (v[i].w - m) * r * g4.w + b4.w;
        o[lane + 32 * i] = ov;
    }
}

// full LN of small matrices (one warp per 512-wide row)
__global__ void ln_full_kernel(const float* __restrict__ x, const float* __restrict__ g,
                               const float* __restrict__ b, float* __restrict__ out, int rows) {
    int warp = (blockIdx.x * blockDim.x + threadIdx.x) >> 5;
    int lane = threadIdx.x & 31;
    if (warp >= rows) return;
    const float4* xr = (const float4*)(x + (size_t)warp * CD);
    float4 v[4];
    float s = 0.f, s2 = 0.f;
#pragma unroll
    for (int i = 0; i < 4; i++) {
        v[i] = xr[lane + 32 * i];
        s  += v[i].x + v[i].y + v[i].z + v[i].w;
        s2 += v[i].x * v[i].x + v[i].y * v[i].y + v[i].z * v[i].z + v[i].w * v[i].w;
    }
    s = warp_sum(s); s2 = warp_sum(s2);
    float m = s * (1.0f / CD);
    float var = s2 * (1.0f / CD) - m * m;
    float r = rsqrtf(var + LN_EPS);
    float4* o = (float4*)(out + (size_t)warp * CD);
    const float4* g4p = (const float4*)g;
    const float4* b4p = (const float4*)b;
#pragma unroll
    for (int i = 0; i < 4; i++) {
        float4 g4 = g4p[lane + 32 * i];
        float4 b4 = b4p[lane + 32 * i];
        float4 ov;
        ov.x = (v[i].x - m) * r * g4.x + b4.x;
        ov.y = (v[i].y - m) * r * g4.y + b4.y;
        ov.z = (v[i].z - m) * r * g4.z + b4.z;
        ov.w = (v[i].w - m) * r * g4.w + b4.w;
        o[lane + 32 * i] = ov;
    }
}

// qkb[row] = q[row] . k_b   (one warp per row, 32 blocks x 8 warps)
__global__ void qkb_kernel(const float* __restrict__ kb) {
    int row = blockIdx.x * 8 + (threadIdx.x >> 5);
    int lane = threadIdx.x & 31;
    const float4* qr = (const float4*)(g_q + (size_t)row * CD);
    const float4* kr = (const float4*)kb;
    float s = 0.f;
#pragma unroll
    for (int i = 0; i < 4; i++) {
        float4 a = qr[lane + 32 * i], c = kr[lane + 32 * i];
        s += a.x * c.x + a.y * c.y + a.z * c.z + a.w * c.w;
    }
    s = warp_sum(s);
    if (lane == 0) g_qkb[row] = s;
}

// ---------------- tf32 mma.sync GEMM core ------------------------------------
template <int ACT>
__device__ __forceinline__ void gemm_core(
    const float* __restrict__ A, int lda,
    const float* __restrict__ W, int ldw,
    const float* __restrict__ bias,
    float* __restrict__ C, int ldc, int K, int m0, int n0,
    float* __restrict__ C2) {
    __shared__ uint32_t As[128][36];
    __shared__ uint32_t Bs[128][36];

    const int warp = threadIdx.x >> 5;
    const int lane = threadIdx.x & 31;
    const int gid = lane >> 2;
    const int tig = lane & 3;
    const int mbase = (warp >> 2) * 64;
    const int nbase = (warp & 3) * 32;

    float c[4][4][4];
#pragma unroll
    for (int mi = 0; mi < 4; mi++)
#pragma unroll
        for (int ni = 0; ni < 4; ni++)
#pragma unroll
            for (int r = 0; r < 4; r++) c[mi][ni][r] = 0.f;

    for (int kt = 0; kt < K; kt += 32) {
#pragma unroll
        for (int it = 0; it < 4; it++) {
            int f = threadIdx.x + it * 256;
            int r = f >> 3;
            int c4 = (f & 7) << 2;
            {
                float4 x = *(const float4*)(A + (size_t)(m0 + r) * lda + kt + c4);
                As[r][c4 + 0] = f2tf(x.x); As[r][c4 + 1] = f2tf(x.y);
                As[r][c4 + 2] = f2tf(x.z); As[r][c4 + 3] = f2tf(x.w);
            }
            {
                float4 w4 = *(const float4*)(W + (size_t)(n0 + r) * ldw + kt + c4);
                Bs[r][c4 + 0] = f2tf(w4.x); Bs[r][c4 + 1] = f2tf(w4.y);
                Bs[r][c4 + 2] = f2tf(w4.z); Bs[r][c4 + 3] = f2tf(w4.w);
            }
        }
        __syncthreads();
#pragma unroll
        for (int ks = 0; ks < 4; ks++) {
            uint32_t a[4][4], bf[4][2];
            int kk = ks * 8 + tig;
#pragma unroll
            for (int mi = 0; mi < 4; mi++) {
                int row = mbase + mi * 16 + gid;
                a[mi][0] = As[row][kk];
                a[mi][1] = As[row + 8][kk];
                a[mi][2] = As[row][kk + 4];
                a[mi][3] = As[row + 8][kk + 4];
            }
#pragma unroll
            for (int ni = 0; ni < 4; ni++) {
                int col = nbase + ni * 8 + gid;
                bf[ni][0] = Bs[col][kk];
                bf[ni][1] = Bs[col][kk + 4];
            }
#pragma unroll
            for (int mi = 0; mi < 4; mi++)
#pragma unroll
                for (int ni = 0; ni < 4; ni++) mma_tf32(c[mi][ni], a[mi], bf[ni]);
        }
        __syncthreads();
    }

#pragma unroll
    for (int mi = 0; mi < 4; mi++) {
        int r0 = m0 + mbase + mi * 16 + gid;
#pragma unroll
        for (int ni = 0; ni < 4; ni++) {
            int col = n0 + nbase + ni * 8 + tig * 2;
            float bv0 = bias ? __ldg(bias + col) : 0.f;
            float bv1 = bias ? __ldg(bias + col + 1) : 0.f;
            float v00 = c[mi][ni][0] + bv0, v01 = c[mi][ni][1] + bv1;
            float v10 = c[mi][ni][2] + bv0, v11 = c[mi][ni][3] + bv1;
            if (ACT == 1) { v00 = geluf(v00); v01 = geluf(v01); v10 = geluf(v10); v11 = geluf(v11); }
            *(float2*)(C + (size_t)r0 * ldc + col)       = make_float2(v00, v01);
            *(float2*)(C + (size_t)(r0 + 8) * ldc + col) = make_float2(v10, v11);
            if (C2) {
                *(float2*)(C2 + (size_t)r0 * ldc + col)       = make_float2(v00, v01);
                *(float2*)(C2 + (size_t)(r0 + 8) * ldc + col) = make_float2(v10, v11);
            }
        }
    }
}

template <int ACT>
__global__ __launch_bounds__(256) void gemm_tf32(
    const float* __restrict__ A, int lda,
    const float* __restrict__ W, int ldw,
    const float* __restrict__ bias,
    float* __restrict__ C, int ldc, int K, float* __restrict__ C2) {
    gemm_core<ACT>(A, lda, W, ldw, bias, C, ldc, K, blockIdx.y * 128, blockIdx.x * 128, C2);
}

// merged GRU pair: z=0 -> gi = updates @ w_ih^T + b_ih ; z=1 -> gh = slots @ w_hh^T + b_hh
__global__ __launch_bounds__(256) void gru_gemm_dual(
    const float* __restrict__ w_ih, const float* __restrict__ w_hh,
    const float* __restrict__ b_ih, const float* __restrict__ b_hh) {
    const float* A = (blockIdx.z == 0) ? g_updates : g_slots;
    const float* W = (blockIdx.z == 0) ? w_ih : w_hh;
    const float* bias = (blockIdx.z == 0) ? b_ih : b_hh;
    float* C = (blockIdx.z == 0) ? g_gi : g_gh;
    gemm_core<0>(A, 512, W, 512, bias, C, 1536, 512, blockIdx.y * 128, blockIdx.x * 128, nullptr);
}

// ---------------- fused attention pass ---------------------------------------
// grid (chunk=8, b=32), 256 threads. One pass over x_ln chunk (256 tokens):
// dots (qk . x + qkb) -> softmax over 8 slots -> partial sm-weighted x sums,
// partial softmax sums, partial x sums.
#define FA_QKS   0                      // 4096 floats
#define FA_TILE  4096                   // 2 x 8192 floats (16 tok x 512)
#define FA_SMS   (4096 + 16384)         // 128 floats
#define FA_WSS   (FA_SMS + 128)         // 64 floats
#define FA_QKB   (FA_WSS + 64)          // 8 floats
#define FA_FLOATS (FA_QKB + 8)
#define FA_SMEM  (FA_FLOATS * 4)        // 82720 B

__global__ void __launch_bounds__(256, 2) fused_attn_kernel() {
    extern __shared__ float sm[];
    float* qks  = sm + FA_QKS;
    float* tile = sm + FA_TILE;
    float* sms  = sm + FA_SMS;
    float* wss  = sm + FA_WSS;
    float* qkbs = sm + FA_QKB;
    const uint32_t tile_u = smem_u32(tile);

    const int chunk = blockIdx.x;
    const int b     = blockIdx.y;
    const int tid   = threadIdx.x;
    const int warp  = tid >> 5;
    const int lane  = tid & 31;

    // load qk rows for this batch (8 x 512) + qkb
    {
        const float4* src = (const float4*)(g_qk + (size_t)b * 4096);
        float4* dst = (float4*)qks;
        for (int f = tid; f < 1024; f += 256) dst[f] = src[f];
        if (tid < 8) qkbs[tid] = g_qkb[b * 8 + tid];
    }

    const size_t jbase = (size_t)(b * CN + chunk * 256) * CD;
    // issue subtile 0
#define FA_ISSUE(ST)                                                               \
    do {                                                                           \
        uint32_t dst = tile_u + ((ST) & 1) * (8192 * 4);                           \
        _Pragma("unroll")                                                          \
        for (int i = 0; i < 8; i++) {                                              \
            int idx = tid + i * 256;                                               \
            int r = idx >> 7, c4 = (idx & 127) * 4;                                \
            cpa16(dst + (r * 512 + c4) * 4, g_xln + jbase + (size_t)((ST) * 16 + r) * 512 + c4); \
        }                                                                          \
        CPA_COMMIT();                                                              \
    } while (0)

    FA_ISSUE(0);

    float accA[8], accB[8], accx0 = 0.f, accx1 = 0.f, ssw[8];
#pragma unroll
    for (int s = 0; s < 8; s++) { accA[s] = 0.f; accB[s] = 0.f; ssw[s] = 0.f; }
    const int d0 = tid, d1 = tid + 256;

#pragma unroll 1
    for (int st = 0; st < 16; st++) {
        __syncthreads();                       // prior Phase B fully done
        if (st + 1 < 16) { FA_ISSUE(st + 1); CPA_WAIT1(); }
        else             { CPA_WAIT0(); }
        __syncthreads();                       // tile(st) visible
        float* tc = tile + (st & 1) * 8192;

        // Phase A: dots + softmax; warp handles 2 tokens
#pragma unroll
        for (int tk = 0; tk < 2; tk++) {
            int tok = warp * 2 + tk;
            const float4* xr = (const float4*)(tc + tok * 512);
            float acc[8];
#pragma unroll
            for (int s = 0; s < 8; s++) acc[s] = 0.f;
#pragma unroll
            for (int cc = 0; cc < 4; cc++) {
                float4 x4 = xr[cc * 32 + lane];
#pragma unroll
                for (int s = 0; s < 8; s++) {
                    float4 q4 = ((const float4*)qks)[s * 128 + cc * 32 + lane];
                    acc[s] += x4.x * q4.x + x4.y * q4.y + x4.z * q4.z + x4.w * q4.w;
                }
            }
#pragma unroll
            for (int o = 16; o; o >>= 1)
#pragma unroll
                for (int s = 0; s < 8; s++) acc[s] += __shfl_xor_sync(0xffffffffu, acc[s], o);
#pragma unroll
            for (int s = 0; s < 8; s++) acc[s] += qkbs[s];
            float mx = acc[0];
#pragma unroll
            for (int s = 1; s < 8; s++) mx = fmaxf(mx, acc[s]);
            float e[8], sum = 0.f;
#pragma unroll
            for (int s = 0; s < 8; s++) { e[s] = expf((acc[s] - mx) * ATT_SCALE); sum += e[s]; }
            float inv = 1.0f / sum;
#pragma unroll
            for (int s = 0; s < 8; s++) ssw[s] += e[s] * inv;
            float val = 0.f;
#pragma unroll
            for (int s = 0; s < 8; s++) if (lane == s) val = e[s] * inv;
            if (lane < 8) sms[tok * 8 + lane] = val;
        }
        __syncthreads();                       // sms visible

        // Phase B: weighted accumulation; thread owns cols d0, d1
#pragma unroll
        for (int j = 0; j < 16; j++) {
            float4 s0 = *(const float4*)(sms + j * 8);
            float4 s1 = *(const float4*)(sms + j * 8 + 4);
            float x0 = tc[j * 512 + d0];
            float x1 = tc[j * 512 + d1];
            accA[0] += s0.x * x0; accB[0] += s0.x * x1;
            accA[1] += s0.y * x0; accB[1] += s0.y * x1;
            accA[2] += s0.z * x0; accB[2] += s0.z * x1;
            accA[3] += s0.w * x0; accB[3] += s0.w * x1;
            accA[4] += s1.x * x0; accB[4] += s1.x * x1;
            accA[5] += s1.y * x0; accB[5] += s1.y * x1;
            accA[6] += s1.z * x0; accB[6] += s1.z * x1;
            accA[7] += s1.w * x0; accB[7] += s1.w * x1;
            accx0 += x0; accx1 += x1;
        }
    }
#undef FA_ISSUE

    // write partials
#pragma unroll
    for (int s = 0; s < 8; s++) {
        size_t row = (size_t)(chunk * 256 + b * 8 + s) * 512;
        g_paw[row + d0] = accA[s];
        g_paw[row + d1] = accB[s];
    }
    g_pxsum[(size_t)(chunk * 32 + b) * 512 + d0] = accx0;
    g_pxsum[(size_t)(chunk * 32 + b) * 512 + d1] = accx1;
    // ssum: identical across lanes; warp 0..7 each contributes
    if (lane == 0) {
#pragma unroll
        for (int s = 0; s < 8; s++) wss[warp * 8 + s] = ssw[s];
    }
    __syncthreads();
    if (tid < 8) {
        float t = 0.f;
#pragma unroll
        for (int w = 0; w < 8; w++) t += wss[w * 8 + tid];
        g_pssum[chunk * 256 + b * 8 + tid] = t;
    }
}

// compose aw = (sum_chunks paw + EPS*xsum) / (sum_chunks ssum + N*EPS)
__global__ void aw_compose_kernel() {
    int idx = blockIdx.x * 256 + threadIdx.x;    // 131072
    int row = idx >> 9;                          // b*8+s
    int d = idx & 511;
    int b = row >> 3;
    float den = 0.f, tot = 0.f, xs = 0.f;
#pragma unroll
    for (int c = 0; c < 8; c++) {
        den += g_pssum[c * 256 + row];
        tot += g_paw[(size_t)c * 131072 + (size_t)row * 512 + d];
        xs  += g_pxsum[(size_t)c * 16384 + (size_t)b * 512 + d];
    }
    float inv = 1.0f / (den + (float)CN * EPS_A);
    g_aw[idx] = (tot + EPS_A * xs) * inv;
}

__global__ void gru_elem_kernel() {
    int idx = blockIdx.x * 256 + threadIdx.x;
    int r = idx >> 9, d = idx & 511;
    const float* gir = g_gi + (size_t)r * 1536;
    const float* ghr = g_gh + (size_t)r * 1536;
    float i_r = gir[d], i_z = gir[d + 512], i_n = gir[d + 1024];
    float h_r = ghr[d], h_z = ghr[d + 512], h_n = ghr[d + 1024];
    float rg = sigm(i_r + h_r);
    float z  = sigm(i_z + h_z);
    float nn = tanhf(i_n + rg * h_n);
    float h  = g_slots[idx];
    float h_new = (1.0f - z) * nn + z * h;
    g_slots[idx] = g_updates[idx] + h_new;
}

// ---------------- launcher --------------------------------------------------
#define SYM(p, s) do { void* _v = nullptr; cudaGetSymbolAddress(&_v, s); (p) = (float*)_v; } while (0)

extern "C" void kernel_launch(void* const* d_in, const int* in_sizes, int n_in,
                              void* d_out, int out_size) {
    (void)in_sizes; (void)n_in; (void)out_size;
    const float* inputs         = (const float*)d_in[0];
    const float* slot_noise     = (const float*)d_in[1];
    const float* slots_mu       = (const float*)d_in[2];
    const float* slots_logsigma = (const float*)d_in[3];
    const float* k_w  = (const float*)d_in[4];
    const float* k_b  = (const float*)d_in[5];
    const float* v_w  = (const float*)d_in[6];
    const float* v_b  = (const float*)d_in[7];
    const float* gru_w_ih = (const float*)d_in[8];
    const float* gru_w_hh = (const float*)d_in[9];
    const float* gru_b_ih = (const float*)d_in[10];
    const float* gru_b_hh = (const float*)d_in[11];
    const float* ln_in_g = (const float*)d_in[12];
    const float* ln_in_b = (const float*)d_in[13];
    const float* ln_slots_g = (const float*)d_in[14];
    const float* ln_slots_b = (const float*)d_in[15];
    const float* ln_pre_g = (const float*)d_in[16];
    const float* ln_pre_b = (const float*)d_in[17];
    const float* mlp1_w = (const float*)d_in[18];
    const float* mlp1_b = (const float*)d_in[19];
    const float* mlp2_w = (const float*)d_in[20];
    const float* mlp2_b = (const float*)d_in[21];
    const float* mlp3_w = (const float*)d_in[22];
    const float* mlp3_b = (const float*)d_in[23];
    const float* mlp4_w = (const float*)d_in[24];
    const float* mlp4_b = (const float*)d_in[25];
    float* out = (float*)d_out;

    float *p_slots, *p_q, *p_qk, *p_kwT, *p_aw, *p_upd, *p_s0, *p_h1, *p_h2, *p_h3;
    SYM(p_slots, g_slots); SYM(p_q, g_q); SYM(p_qk, g_qk); SYM(p_kwT, g_kwT);
    SYM(p_aw, g_aw); SYM(p_upd, g_updates); SYM(p_s0, g_s0);
    SYM(p_h1, g_h1); SYM(p_h2, g_h2); SYM(p_h3, g_h3);

    cudaFuncSetAttribute(fused_attn_kernel, cudaFuncAttributeMaxDynamicSharedMemorySize, FA_SMEM);

    slot_init_kernel<<<512, 256>>>(slot_noise, slots_mu, slots_logsigma);
    transpose_kw_kernel<<<dim3(16, 16), dim3(32, 8)>>>(k_w);
    ln_writeX_kernel<<<8192, 256>>>(inputs, ln_in_g, ln_in_b);

    for (int it = 0; it < 3; it++) {
        ln_full_kernel<<<32, 256>>>(p_slots, ln_slots_g, ln_slots_b, p_q, SROWS);
        // qk = q (contract) kw  -> [256,512]
        gemm_tf32<0><<<dim3(4, 2), 256>>>(p_q, 512, p_kwT, 512, nullptr, p_qk, 512, 512, nullptr);
        qkb_kernel<<<32, 256>>>(k_b);
        fused_attn_kernel<<<dim3(8, 32), 256, FA_SMEM>>>();
        aw_compose_kernel<<<512, 256>>>();
        // updates = aw @ v_w^T + v_b  (last iter also writes output slot 0)
        gemm_tf32<0><<<dim3(4, 2), 256>>>(p_aw, 512, v_w, 512, v_b, p_upd, 512, 512,
                                          (it == 2) ? out : nullptr);
        gru_gemm_dual<<<dim3(12, 2, 2), 256>>>(gru_w_ih, gru_w_hh, gru_b_ih, gru_b_hh);
        gru_elem_kernel<<<512, 256>>>();
    }

    ln_full_kernel<<<32, 256>>>(p_slots, ln_pre_g, ln_pre_b, p_s0, SROWS);
    gemm_tf32<1><<<dim3(8, 2), 256>>>(p_s0, 512, mlp1_w, 512, mlp1_b, p_h1, 1024, 512, nullptr);
    gemm_tf32<1><<<dim3(8, 2), 256>>>(p_h1, 1024, mlp2_w, 1024, mlp2_b, p_h2, 1024, 1024, nullptr);
    gemm_tf32<1><<<dim3(4, 2), 256>>>(p_h2, 1024, mlp3_w, 1024, mlp3_b, p_h3, 512, 1024, nullptr);
    gemm_tf32<0><<<dim3(2, 2), 256>>>(p_h3, 512, mlp4_w, 512, mlp4_b, out + 131072, 256, 512, nullptr);
}

// round 6
// speedup vs baseline: 2.6091x; 1.5329x over previous
#include <cuda_runtime.h>
#include <stdint.h>
#include <math.h>

// Problem constants
#define CB   32
#define CN   2048
#define CD   512
#define CNS  8
#define MROWS 65536          // CB*CN
#define SROWS 256            // CB*CNS
#define EPS_A 1e-8f
#define LN_EPS 1e-5f
#define ATT_SCALE 0.044194173824159216f  // 512^-0.5

// ---------------- scratch (device globals; no allocation allowed) ----------
__device__ float g_xln[33554432];    // [65536][512] LN(inputs), fp32
__device__ float g_kwT[262144];      // kw transposed
__device__ float g_slots[131072];    // [256][512]
__device__ float g_q[131072];        // LN(slots)
__device__ float g_qk[131072];       // q contracted with kw
__device__ float g_qkb[256];         // q . k_b
__device__ float g_paw[1048576];     // [8 chunk][256][512] partial sm-weighted x
__device__ float g_pssum[2048];      // [8 chunk][256] partial softmax sums
__device__ float g_pxsum[131072];    // [8 chunk][32][512] partial x sums
__device__ float g_aw[131072];       // attention-weighted x (normalized)
__device__ float g_updates[131072];
__device__ float g_gi[393216];       // [256][1536]
__device__ float g_gh[393216];
__device__ float g_s0[131072];
__device__ float g_h1[262144];
__device__ float g_h2[262144];
__device__ float g_h3[131072];

// ---------------- small helpers -------------------------------------------
__device__ __forceinline__ uint32_t f2tf(float f) {
    uint32_t u; asm("cvt.rna.tf32.f32 %0, %1;" : "=r"(u) : "f"(f)); return u;
}
__device__ __forceinline__ float geluf(float x) {
    return 0.5f * x * (1.0f + erff(x * 0.7071067811865476f));
}
__device__ __forceinline__ float sigm(float x) { return 1.0f / (1.0f + expf(-x)); }
__device__ __forceinline__ float warp_sum(float v) {
#pragma unroll
    for (int o = 16; o; o >>= 1) v += __shfl_xor_sync(0xffffffffu, v, o);
    return v;
}
__device__ __forceinline__ void mma_tf32(float c[4], const uint32_t a[4], const uint32_t b[2]) {
    asm volatile(
        "mma.sync.aligned.m16n8k8.row.col.f32.tf32.tf32.f32 "
        "{%0,%1,%2,%3}, {%4,%5,%6,%7}, {%8,%9}, {%0,%1,%2,%3};\n"
        : "+f"(c[0]), "+f"(c[1]), "+f"(c[2]), "+f"(c[3])
        : "r"(a[0]), "r"(a[1]), "r"(a[2]), "r"(a[3]), "r"(b[0]), "r"(b[1]));
}
__device__ __forceinline__ uint32_t smem_u32(const void* p) {
    uint32_t a;
    asm("{ .reg .u64 t; cvta.to.shared.u64 t, %1; cvt.u32.u64 %0, t; }" : "=r"(a) : "l"(p));
    return a;
}
__device__ __forceinline__ void cpa16(uint32_t dst, const void* src) {
    asm volatile("cp.async.cg.shared.global [%0], [%1], 16;" :: "r"(dst), "l"(src));
}
#define CPA_COMMIT() asm volatile("cp.async.commit_group;" ::: "memory")
#define CPA_WAIT1()  asm volatile("cp.async.wait_group 1;" ::: "memory")
#define CPA_WAIT0()  asm volatile("cp.async.wait_group 0;" ::: "memory")

// ---------------- prologue kernels -----------------------------------------
__global__ void slot_init_kernel(const float* __restrict__ noise, const float* __restrict__ mu,
                                 const float* __restrict__ ls) {
    int idx = blockIdx.x * 256 + threadIdx.x;        // 131072
    int d = idx & 511;
    g_slots[idx] = mu[d] + expf(ls[d]) * noise[idx];
}

__global__ void transpose_kw_kernel(const float* __restrict__ kw) {
    __shared__ float t[32][33];
    int bx = blockIdx.x * 32, by = blockIdx.y * 32;
    int tx = threadIdx.x, ty = threadIdx.y;     // 32 x 8
#pragma unroll
    for (int i = 0; i < 32; i += 8)
        t[ty + i][tx] = kw[(size_t)(by + ty + i) * 512 + bx + tx];
    __syncthreads();
#pragma unroll
    for (int i = 0; i < 32; i += 8)
        g_kwT[(size_t)(bx + ty + i) * 512 + by + tx] = t[tx][ty + i];
}

// LN(inputs) -> g_xln (full fp32, one warp per row)
__global__ void ln_writeX_kernel(const float* __restrict__ x, const float* __restrict__ g,
                                 const float* __restrict__ b) {
    int warp = (blockIdx.x * blockDim.x + threadIdx.x) >> 5;
    int lane = threadIdx.x & 31;
    if (warp >= MROWS) return;
    const float4* xr = (const float4*)(x + (size_t)warp * CD);
    float4 v[4];
    float s = 0.f, s2 = 0.f;
#pragma unroll
    for (int i = 0; i < 4; i++) {
        v[i] = xr[lane + 32 * i];
        s  += v[i].x + v[i].y + v[i].z + v[i].w;
        s2 += v[i].x * v[i].x + v[i].y * v[i].y + v[i].z * v[i].z + v[i].w * v[i].w;
    }
    s = warp_sum(s); s2 = warp_sum(s2);
    float m = s * (1.0f / CD);
    float var = s2 * (1.0f / CD) - m * m;
    float r = rsqrtf(var + LN_EPS);
    float4* o = (float4*)(g_xln + (size_t)warp * CD);
    const float4* g4p = (const float4*)g;
    const float4* b4p = (const float4*)b;
#pragma unroll
    for (int i = 0; i < 4; i++) {
        float4 g4 = g4p[lane + 32 * i];
        float4 b4 = b4p[lane + 32 * i];
        float4 ov;
        ov.x = (v[i].x - m) * r * g4.x + b4.x;
        ov.y = (v[i].y - m) * r * g4.y + b4.y;
        ov.z = (v[i].z - m) * r * g4.z + b4.z;
        ov.w = (v[i].w - m) * r * g4.w + b4.w;
        o[lane + 32 * i] = ov;
    }
}

// LN of slots -> out, optionally fused qkb = out . k_b
__global__ void ln_q_kernel(const float* __restrict__ x, const float* __restrict__ g,
                            const float* __restrict__ b, float* __restrict__ out,
                            const float* __restrict__ kb) {
    int warp = (blockIdx.x * blockDim.x + threadIdx.x) >> 5;
    int lane = threadIdx.x & 31;
    if (warp >= SROWS) return;
    const float4* xr = (const float4*)(x + (size_t)warp * CD);
    float4 v[4];
    float s = 0.f, s2 = 0.f;
#pragma unroll
    for (int i = 0; i < 4; i++) {
        v[i] = xr[lane + 32 * i];
        s  += v[i].x + v[i].y + v[i].z + v[i].w;
        s2 += v[i].x * v[i].x + v[i].y * v[i].y + v[i].z * v[i].z + v[i].w * v[i].w;
    }
    s = warp_sum(s); s2 = warp_sum(s2);
    float m = s * (1.0f / CD);
    float var = s2 * (1.0f / CD) - m * m;
    float r = rsqrtf(var + LN_EPS);
    float4* o = (float4*)(out + (size_t)warp * CD);
    const float4* g4p = (const float4*)g;
    const float4* b4p = (const float4*)b;
    const float4* k4p = (const float4*)kb;
    float qdot = 0.f;
#pragma unroll
    for (int i = 0; i < 4; i++) {
        float4 g4 = g4p[lane + 32 * i];
        float4 b4 = b4p[lane + 32 * i];
        float4 ov;
        ov.x = (v[i].x - m) * r * g4.x + b4.x;
        ov.y = (v[i].y - m) * r * g4.y + b4.y;
        ov.z = (v[i].z - m) * r * g4.z + b4.z;
        ov.w = (v[i].w - m) * r * g4.w + b4.w;
        o[lane + 32 * i] = ov;
        if (kb) {
            float4 k4 = k4p[lane + 32 * i];
            qdot += ov.x * k4.x + ov.y * k4.y + ov.z * k4.z + ov.w * k4.w;
        }
    }
    if (kb) {
        qdot = warp_sum(qdot);
        if (lane == 0) g_qkb[warp] = qdot;
    }
}

// ---------------- pipelined tf32 GEMM (cp.async, 3 stages) -------------------
#define GP_STRIDE 36
#define GP_TILE   (128 * GP_STRIDE)
#define GP_TILE_B (GP_TILE * 4)
#define GP_SMEM   (3 * 2 * GP_TILE_B)   // 110592

template <int ACT>
__device__ __forceinline__ void gemm_core_pipe(
    const float* __restrict__ A, int lda,
    const float* __restrict__ W, int ldw,
    const float* __restrict__ bias,
    float* __restrict__ C, int ldc, int K, int m0, int n0,
    float* __restrict__ C2) {
    extern __shared__ float sm[];
    float* As = sm;
    float* Bs = sm + 3 * GP_TILE;
    const uint32_t sa = smem_u32(As);
    const uint32_t sb = smem_u32(Bs);

    const int tid = threadIdx.x;
    const int warp = tid >> 5;
    const int lane = tid & 31;
    const int gid = lane >> 2;
    const int tig = lane & 3;
    const int mbase = (warp >> 2) * 64;
    const int nbase = (warp & 3) * 32;

    const int cr = tid >> 3;           // 0..31
    const int cc4 = (tid & 7) * 4;

    float c[4][4][4];
#pragma unroll
    for (int mi = 0; mi < 4; mi++)
#pragma unroll
        for (int ni = 0; ni < 4; ni++)
#pragma unroll
            for (int r = 0; r < 4; r++) c[mi][ni][r] = 0.f;

    const int NT = K >> 5;

#define GP_ISSUE(KT, ST)                                                           \
    do {                                                                           \
        uint32_t a_s = sa + (ST) * GP_TILE_B;                                      \
        uint32_t b_s = sb + (ST) * GP_TILE_B;                                      \
        _Pragma("unroll")                                                          \
        for (int i = 0; i < 4; i++) {                                              \
            int r = cr + i * 32;                                                   \
            cpa16(a_s + (r * GP_STRIDE + cc4) * 4,                                 \
                  A + (size_t)(m0 + r) * lda + (KT) * 32 + cc4);                   \
            cpa16(b_s + (r * GP_STRIDE + cc4) * 4,                                 \
                  W + (size_t)(n0 + r) * ldw + (KT) * 32 + cc4);                   \
        }                                                                          \
        CPA_COMMIT();                                                              \
    } while (0)

    GP_ISSUE(0, 0);
    GP_ISSUE(1, 1);

#pragma unroll 1
    for (int kt = 0; kt < NT; kt++) {
        if (kt < NT - 1) CPA_WAIT1(); else CPA_WAIT0();
        __syncthreads();
        if (kt + 2 < NT) GP_ISSUE(kt + 2, (kt + 2) % 3);

        const float* At = As + (kt % 3) * GP_TILE;
        const float* Bt = Bs + (kt % 3) * GP_TILE;
#pragma unroll
        for (int ks = 0; ks < 4; ks++) {
            uint32_t a[4][4], bf[4][2];
            int kk = ks * 8 + tig;
#pragma unroll
            for (int mi = 0; mi < 4; mi++) {
                const float* ap = At + (mbase + mi * 16 + gid) * GP_STRIDE;
                a[mi][0] = f2tf(ap[kk]);
                a[mi][1] = f2tf(ap[8 * GP_STRIDE + kk]);
                a[mi][2] = f2tf(ap[kk + 4]);
                a[mi][3] = f2tf(ap[8 * GP_STRIDE + kk + 4]);
            }
#pragma unroll
            for (int ni = 0; ni < 4; ni++) {
                const float* bp = Bt + (nbase + ni * 8 + gid) * GP_STRIDE;
                bf[ni][0] = f2tf(bp[kk]);
                bf[ni][1] = f2tf(bp[kk + 4]);
            }
#pragma unroll
            for (int mi = 0; mi < 4; mi++)
#pragma unroll
                for (int ni = 0; ni < 4; ni++) mma_tf32(c[mi][ni], a[mi], bf[ni]);
        }
        __syncthreads();
    }
#undef GP_ISSUE

#pragma unroll
    for (int mi = 0; mi < 4; mi++) {
        int r0 = m0 + mbase + mi * 16 + gid;
#pragma unroll
        for (int ni = 0; ni < 4; ni++) {
            int col = n0 + nbase + ni * 8 + tig * 2;
            float bv0 = bias ? __ldg(bias + col) : 0.f;
            float bv1 = bias ? __ldg(bias + col + 1) : 0.f;
            float v00 = c[mi][ni][0] + bv0, v01 = c[mi][ni][1] + bv1;
            float v10 = c[mi][ni][2] + bv0, v11 = c[mi][ni][3] + bv1;
            if (ACT == 1) { v00 = geluf(v00); v01 = geluf(v01); v10 = geluf(v10); v11 = geluf(v11); }
            *(float2*)(C + (size_t)r0 * ldc + col)       = make_float2(v00, v01);
            *(float2*)(C + (size_t)(r0 + 8) * ldc + col) = make_float2(v10, v11);
            if (C2) {
                *(float2*)(C2 + (size_t)r0 * ldc + col)       = make_float2(v00, v01);
                *(float2*)(C2 + (size_t)(r0 + 8) * ldc + col) = make_float2(v10, v11);
            }
        }
    }
}

template <int ACT>
__global__ __launch_bounds__(256) void gemm_tf32(
    const float* __restrict__ A, int lda,
    const float* __restrict__ W, int ldw,
    const float* __restrict__ bias,
    float* __restrict__ C, int ldc, int K, float* __restrict__ C2) {
    gemm_core_pipe<ACT>(A, lda, W, ldw, bias, C, ldc, K, blockIdx.y * 128, blockIdx.x * 128, C2);
}

// merged GRU pair
__global__ __launch_bounds__(256) void gru_gemm_dual(
    const float* __restrict__ w_ih, const float* __restrict__ w_hh,
    const float* __restrict__ b_ih, const float* __restrict__ b_hh) {
    const float* A = (blockIdx.z == 0) ? g_updates : g_slots;
    const float* W = (blockIdx.z == 0) ? w_ih : w_hh;
    const float* bias = (blockIdx.z == 0) ? b_ih : b_hh;
    float* C = (blockIdx.z == 0) ? g_gi : g_gh;
    gemm_core_pipe<0>(A, 512, W, 512, bias, C, 1536, 512, blockIdx.y * 128, blockIdx.x * 128, nullptr);
}

// ---------------- fused attention pass ---------------------------------------
#define FA_QKS   0
#define FA_TILE  4096
#define FA_SMS   (4096 + 16384)
#define FA_WSS   (FA_SMS + 128)
#define FA_QKB   (FA_WSS + 64)
#define FA_FLOATS (FA_QKB + 8)
#define FA_SMEM  (FA_FLOATS * 4)

__global__ void __launch_bounds__(256, 2) fused_attn_kernel() {
    extern __shared__ float sm[];
    float* qks  = sm + FA_QKS;
    float* tile = sm + FA_TILE;
    float* sms  = sm + FA_SMS;
    float* wss  = sm + FA_WSS;
    float* qkbs = sm + FA_QKB;
    const uint32_t tile_u = smem_u32(tile);

    const int chunk = blockIdx.x;
    const int b     = blockIdx.y;
    const int tid   = threadIdx.x;
    const int warp  = tid >> 5;
    const int lane  = tid & 31;

    {
        const float4* src = (const float4*)(g_qk + (size_t)b * 4096);
        float4* dst = (float4*)qks;
        for (int f = tid; f < 1024; f += 256) dst[f] = src[f];
        if (tid < 8) qkbs[tid] = g_qkb[b * 8 + tid];
    }

    const size_t jbase = (size_t)(b * CN + chunk * 256) * CD;
#define FA_ISSUE(ST)                                                               \
    do {                                                                           \
        uint32_t dst = tile_u + ((ST) & 1) * (8192 * 4);                           \
        _Pragma("unroll")                                                          \
        for (int i = 0; i < 8; i++) {                                              \
            int idx = tid + i * 256;                                               \
            int r = idx >> 7, c4 = (idx & 127) * 4;                                \
            cpa16(dst + (r * 512 + c4) * 4, g_xln + jbase + (size_t)((ST) * 16 + r) * 512 + c4); \
        }                                                                          \
        CPA_COMMIT();                                                              \
    } while (0)

    FA_ISSUE(0);

    float accA[8], accB[8], accx0 = 0.f, accx1 = 0.f, ssw[8];
#pragma unroll
    for (int s = 0; s < 8; s++) { accA[s] = 0.f; accB[s] = 0.f; ssw[s] = 0.f; }
    const int d0 = tid, d1 = tid + 256;

#pragma unroll 1
    for (int st = 0; st < 16; st++) {
        __syncthreads();
        if (st + 1 < 16) { FA_ISSUE(st + 1); CPA_WAIT1(); }
        else             { CPA_WAIT0(); }
        __syncthreads();
        float* tc = tile + (st & 1) * 8192;

        // Phase A: dots for both of this warp's tokens, q4 loaded once
        {
            const int tok0 = warp * 2;
            const float4* xr0 = (const float4*)(tc + tok0 * 512);
            const float4* xr1 = (const float4*)(tc + (tok0 + 1) * 512);
            float a0[8], a1[8];
#pragma unroll
            for (int s = 0; s < 8; s++) { a0[s] = 0.f; a1[s] = 0.f; }
#pragma unroll
            for (int cc = 0; cc < 4; cc++) {
                float4 x0 = xr0[cc * 32 + lane];
                float4 x1 = xr1[cc * 32 + lane];
#pragma unroll
                for (int s = 0; s < 8; s++) {
                    float4 q4 = ((const float4*)qks)[s * 128 + cc * 32 + lane];
                    a0[s] += x0.x * q4.x + x0.y * q4.y + x0.z * q4.z + x0.w * q4.w;
                    a1[s] += x1.x * q4.x + x1.y * q4.y + x1.z * q4.z + x1.w * q4.w;
                }
            }
#pragma unroll
            for (int o = 16; o; o >>= 1)
#pragma unroll
                for (int s = 0; s < 8; s++) {
                    a0[s] += __shfl_xor_sync(0xffffffffu, a0[s], o);
                    a1[s] += __shfl_xor_sync(0xffffffffu, a1[s], o);
                }
#pragma unroll
            for (int tk = 0; tk < 2; tk++) {
                float acc[8];
#pragma unroll
                for (int s = 0; s < 8; s++) acc[s] = (tk ? a1[s] : a0[s]) + qkbs[s];
                float mx = acc[0];
#pragma unroll
                for (int s = 1; s < 8; s++) mx = fmaxf(mx, acc[s]);
                float e[8], sum = 0.f;
#pragma unroll
                for (int s = 0; s < 8; s++) { e[s] = expf((acc[s] - mx) * ATT_SCALE); sum += e[s]; }
                float inv = 1.0f / sum;
#pragma unroll
                for (int s = 0; s < 8; s++) ssw[s] += e[s] * inv;
                float val = 0.f;
#pragma unroll
                for (int s = 0; s < 8; s++) if (lane == s) val = e[s] * inv;
                if (lane < 8) sms[(tok0 + tk) * 8 + lane] = val;
            }
        }
        __syncthreads();

        // Phase B
#pragma unroll
        for (int j = 0; j < 16; j++) {
            float4 s0 = *(const float4*)(sms + j * 8);
            float4 s1 = *(const float4*)(sms + j * 8 + 4);
            float x0 = tc[j * 512 + d0];
            float x1 = tc[j * 512 + d1];
            accA[0] += s0.x * x0; accB[0] += s0.x * x1;
            accA[1] += s0.y * x0; accB[1] += s0.y * x1;
            accA[2] += s0.z * x0; accB[2] += s0.z * x1;
            accA[3] += s0.w * x0; accB[3] += s0.w * x1;
            accA[4] += s1.x * x0; accB[4] += s1.x * x1;
            accA[5] += s1.y * x0; accB[5] += s1.y * x1;
            accA[6] += s1.z * x0; accB[6] += s1.z * x1;
            accA[7] += s1.w * x0; accB[7] += s1.w * x1;
            accx0 += x0; accx1 += x1;
        }
    }
#undef FA_ISSUE

#pragma unroll
    for (int s = 0; s < 8; s++) {
        size_t row = (size_t)(chunk * 256 + b * 8 + s) * 512;
        g_paw[row + d0] = accA[s];
        g_paw[row + d1] = accB[s];
    }
    g_pxsum[(size_t)(chunk * 32 + b) * 512 + d0] = accx0;
    g_pxsum[(size_t)(chunk * 32 + b) * 512 + d1] = accx1;
    if (lane == 0) {
#pragma unroll
        for (int s = 0; s < 8; s++) wss[warp * 8 + s] = ssw[s];
    }
    __syncthreads();
    if (tid < 8) {
        float t = 0.f;
#pragma unroll
        for (int w = 0; w < 8; w++) t += wss[w * 8 + tid];
        g_pssum[chunk * 256 + b * 8 + tid] = t;
    }
}

__global__ void aw_compose_kernel() {
    int idx = blockIdx.x * 256 + threadIdx.x;
    int row = idx >> 9;
    int d = idx & 511;
    int b = row >> 3;
    float den = 0.f, tot = 0.f, xs = 0.f;
#pragma unroll
    for (int c = 0; c < 8; c++) {
        den += g_pssum[c * 256 + row];
        tot += g_paw[(size_t)c * 131072 + (size_t)row * 512 + d];
        xs  += g_pxsum[(size_t)c * 16384 + (size_t)b * 512 + d];
    }
    float inv = 1.0f / (den + (float)CN * EPS_A);
    g_aw[idx] = (tot + EPS_A * xs) * inv;
}

__global__ void gru_elem_kernel() {
    int idx = blockIdx.x * 256 + threadIdx.x;
    int r = idx >> 9, d = idx & 511;
    const float* gir = g_gi + (size_t)r * 1536;
    const float* ghr = g_gh + (size_t)r * 1536;
    float i_r = gir[d], i_z = gir[d + 512], i_n = gir[d + 1024];
    float h_r = ghr[d], h_z = ghr[d + 512], h_n = ghr[d + 1024];
    float rg = sigm(i_r + h_r);
    float z  = sigm(i_z + h_z);
    float nn = tanhf(i_n + rg * h_n);
    float h  = g_slots[idx];
    float h_new = (1.0f - z) * nn + z * h;
    g_slots[idx] = g_updates[idx] + h_new;
}

// ---------------- launcher --------------------------------------------------
#define SYM(p, s) do { void* _v = nullptr; cudaGetSymbolAddress(&_v, s); (p) = (float*)_v; } while (0)

extern "C" void kernel_launch(void* const* d_in, const int* in_sizes, int n_in,
                              void* d_out, int out_size) {
    (void)in_sizes; (void)n_in; (void)out_size;
    const float* inputs         = (const float*)d_in[0];
    const float* slot_noise     = (const float*)d_in[1];
    const float* slots_mu       = (const float*)d_in[2];
    const float* slots_logsigma = (const float*)d_in[3];
    const float* k_w  = (const float*)d_in[4];
    const float* k_b  = (const float*)d_in[5];
    const float* v_w  = (const float*)d_in[6];
    const float* v_b  = (const float*)d_in[7];
    const float* gru_w_ih = (const float*)d_in[8];
    const float* gru_w_hh = (const float*)d_in[9];
    const float* gru_b_ih = (const float*)d_in[10];
    const float* gru_b_hh = (const float*)d_in[11];
    const float* ln_in_g = (const float*)d_in[12];
    const float* ln_in_b = (const float*)d_in[13];
    const float* ln_slots_g = (const float*)d_in[14];
    const float* ln_slots_b = (const float*)d_in[15];
    const float* ln_pre_g = (const float*)d_in[16];
    const float* ln_pre_b = (const float*)d_in[17];
    const float* mlp1_w = (const float*)d_in[18];
    const float* mlp1_b = (const float*)d_in[19];
    const float* mlp2_w = (const float*)d_in[20];
    const float* mlp2_b = (const float*)d_in[21];
    const float* mlp3_w = (const float*)d_in[22];
    const float* mlp3_b = (const float*)d_in[23];
    const float* mlp4_w = (const float*)d_in[24];
    const float* mlp4_b = (const float*)d_in[25];
    float* out = (float*)d_out;

    float *p_slots, *p_q, *p_qk, *p_kwT, *p_aw, *p_upd, *p_s0, *p_h1, *p_h2, *p_h3;
    SYM(p_slots, g_slots); SYM(p_q, g_q); SYM(p_qk, g_qk); SYM(p_kwT, g_kwT);
    SYM(p_aw, g_aw); SYM(p_upd, g_updates); SYM(p_s0, g_s0);
    SYM(p_h1, g_h1); SYM(p_h2, g_h2); SYM(p_h3, g_h3);

    cudaFuncSetAttribute(fused_attn_kernel, cudaFuncAttributeMaxDynamicSharedMemorySize, FA_SMEM);
    cudaFuncSetAttribute(gemm_tf32<0>, cudaFuncAttributeMaxDynamicSharedMemorySize, GP_SMEM);
    cudaFuncSetAttribute(gemm_tf32<1>, cudaFuncAttributeMaxDynamicSharedMemorySize, GP_SMEM);
    cudaFuncSetAttribute(gru_gemm_dual, cudaFuncAttributeMaxDynamicSharedMemorySize, GP_SMEM);

    slot_init_kernel<<<512, 256>>>(slot_noise, slots_mu, slots_logsigma);
    transpose_kw_kernel<<<dim3(16, 16), dim3(32, 8)>>>(k_w);
    ln_writeX_kernel<<<8192, 256>>>(inputs, ln_in_g, ln_in_b);

    for (int it = 0; it < 3; it++) {
        ln_q_kernel<<<32, 256>>>(p_slots, ln_slots_g, ln_slots_b, p_q, k_b);
        gemm_tf32<0><<<dim3(4, 2), 256, GP_SMEM>>>(p_q, 512, p_kwT, 512, nullptr, p_qk, 512, 512, nullptr);
        fused_attn_kernel<<<dim3(8, 32), 256, FA_SMEM>>>();
        aw_compose_kernel<<<512, 256>>>();
        gemm_tf32<0><<<dim3(4, 2), 256, GP_SMEM>>>(p_aw, 512, v_w, 512, v_b, p_upd, 512, 512,
                                                   (it == 2) ? out : nullptr);
        gru_gemm_dual<<<dim3(12, 2, 2), 256, GP_SMEM>>>(gru_w_ih, gru_w_hh, gru_b_ih, gru_b_hh);
        gru_elem_kernel<<<512, 256>>>();
    }

    ln_q_kernel<<<32, 256>>>(p_slots, ln_pre_g, ln_pre_b, p_s0, nullptr);
    gemm_tf32<1><<<dim3(8, 2), 256, GP_SMEM>>>(p_s0, 512, mlp1_w, 512, mlp1_b, p_h1, 1024, 512, nullptr);
    gemm_tf32<1><<<dim3(8, 2), 256, GP_SMEM>>>(p_h1, 1024, mlp2_w, 1024, mlp2_b, p_h2, 1024, 1024, nullptr);
    gemm_tf32<1><<<dim3(4, 2), 256, GP_SMEM>>>(p_h2, 1024, mlp3_w, 1024, mlp3_b, p_h3, 512, 1024, nullptr);
    gemm_tf32<0><<<dim3(2, 2), 256, GP_SMEM>>>(p_h3, 512, mlp4_w, 512, mlp4_b, out + 131072, 256, 512, nullptr);
}

// round 7
// speedup vs baseline: 2.8765x; 1.1025x over previous
#include <cuda_runtime.h>
#include <stdint.h>
#include <math.h>

// Problem constants
#define CB   32
#define CN   2048
#define CD   512
#define CNS  8
#define MROWS 65536          // CB*CN
#define SROWS 256            // CB*CNS
#define EPS_A 1e-8f
#define LN_EPS 1e-5f
#define ATT_SCALE 0.044194173824159216f  // 512^-0.5

// ---------------- scratch (device globals; no allocation allowed) ----------
__device__ float g_xln[33554432];    // [65536][512] LN(inputs), fp32 (written by it0)
__device__ float g_kwT[262144];      // kw transposed
__device__ float g_vwT[262144];      // vw transposed
__device__ float g_wcat[1048576];    // [2048][512]: rows 0-511 v_w, rows 512-2047 w_ih@v_w
__device__ float g_bcat[2048];       // [v_b ; w_ih@v_b + b_ih]
__device__ float g_slots[131072];    // [256][512]
__device__ float g_q[131072];        // LN(slots)
__device__ float g_qk[131072];       // q contracted with kw
__device__ float g_qkb[256];         // q . k_b
__device__ float g_paw[1048576];     // [8 chunk][256][512] partial sm-weighted x
__device__ float g_pssum[2048];      // [8 chunk][256] partial softmax sums
__device__ float g_pxsum[131072];    // [8 chunk][32][512] partial x sums
__device__ float g_aw[131072];       // attention-weighted x (normalized)
__device__ float g_cat[524288];      // [256][2048]: cols 0-511 updates, 512-2047 gi
__device__ float g_gh[393216];       // [256][1536]
__device__ float g_s0[131072];
__device__ float g_h1[262144];
__device__ float g_h2[262144];
__device__ float g_h3[131072];

// ---------------- small helpers -------------------------------------------
__device__ __forceinline__ uint32_t f2tf(float f) {
    uint32_t u; asm("cvt.rna.tf32.f32 %0, %1;" : "=r"(u) : "f"(f)); return u;
}
__device__ __forceinline__ float geluf(float x) {
    return 0.5f * x * (1.0f + erff(x * 0.7071067811865476f));
}
__device__ __forceinline__ float sigm(float x) { return 1.0f / (1.0f + expf(-x)); }
__device__ __forceinline__ float warp_sum(float v) {
#pragma unroll
    for (int o = 16; o; o >>= 1) v += __shfl_xor_sync(0xffffffffu, v, o);
    return v;
}
__device__ __forceinline__ void mma_tf32(float c[4], const uint32_t a[4], const uint32_t b[2]) {
    asm volatile(
        "mma.sync.aligned.m16n8k8.row.col.f32.tf32.tf32.f32 "
        "{%0,%1,%2,%3}, {%4,%5,%6,%7}, {%8,%9}, {%0,%1,%2,%3};\n"
        : "+f"(c[0]), "+f"(c[1]), "+f"(c[2]), "+f"(c[3])
        : "r"(a[0]), "r"(a[1]), "r"(a[2]), "r"(a[3]), "r"(b[0]), "r"(b[1]));
}
__device__ __forceinline__ uint32_t smem_u32(const void* p) {
    uint32_t a;
    asm("{ .reg .u64 t; cvta.to.shared.u64 t, %1; cvt.u32.u64 %0, t; }" : "=r"(a) : "l"(p));
    return a;
}
__device__ __forceinline__ void cpa16(uint32_t dst, const void* src) {
    asm volatile("cp.async.cg.shared.global [%0], [%1], 16;" :: "r"(dst), "l"(src));
}
#define CPA_COMMIT() asm volatile("cp.async.commit_group;" ::: "memory")
#define CPA_WAIT1()  asm volatile("cp.async.wait_group 1;" ::: "memory")
#define CPA_WAIT0()  asm volatile("cp.async.wait_group 0;" ::: "memory")

// ---------------- prologue kernels -----------------------------------------
__global__ void slot_init_kernel(const float* __restrict__ noise, const float* __restrict__ mu,
                                 const float* __restrict__ ls) {
    int idx = blockIdx.x * 256 + threadIdx.x;        // 131072
    int d = idx & 511;
    g_slots[idx] = mu[d] + expf(ls[d]) * noise[idx];
}

// 512x512 transpose
__global__ void transpose512_kernel(const float* __restrict__ src, float* __restrict__ dst) {
    __shared__ float t[32][33];
    int bx = blockIdx.x * 32, by = blockIdx.y * 32;
    int tx = threadIdx.x, ty = threadIdx.y;     // 32 x 8
#pragma unroll
    for (int i = 0; i < 32; i += 8)
        t[ty + i][tx] = src[(size_t)(by + ty + i) * 512 + bx + tx];
    __syncthreads();
#pragma unroll
    for (int i = 0; i < 32; i += 8)
        dst[(size_t)(bx + ty + i) * 512 + by + tx] = t[tx][ty + i];
}

// copy v_w rows into g_wcat[0:512], v_b into g_bcat[0:512]
__global__ void copy_vw_kernel(const float* __restrict__ vw, const float* __restrict__ vb) {
    int idx = blockIdx.x * 256 + threadIdx.x;        // 262144
    g_wcat[idx] = vw[idx];
    if (idx < 512) g_bcat[idx] = vb[idx];
}

// g_bcat[512+j] = w_ih[j] . v_b + b_ih[j]   (one warp per j; grid 192 x 256)
__global__ void bc_kernel(const float* __restrict__ w_ih, const float* __restrict__ v_b,
                          const float* __restrict__ b_ih) {
    int j = blockIdx.x * 8 + (threadIdx.x >> 5);     // 0..1535
    int lane = threadIdx.x & 31;
    const float4* wr = (const float4*)(w_ih + (size_t)j * 512);
    const float4* vb4 = (const float4*)v_b;
    float s = 0.f;
#pragma unroll
    for (int i = 0; i < 4; i++) {
        float4 a = wr[lane + 32 * i], c = vb4[lane + 32 * i];
        s += a.x * c.x + a.y * c.y + a.z * c.z + a.w * c.w;
    }
    s = warp_sum(s);
    if (lane == 0) g_bcat[512 + j] = s + b_ih[j];
}

// LN of slots -> out, optionally fused qkb = out . k_b
__global__ void ln_q_kernel(const float* __restrict__ x, const float* __restrict__ g,
                            const float* __restrict__ b, float* __restrict__ out,
                            const float* __restrict__ kb) {
    int warp = (blockIdx.x * blockDim.x + threadIdx.x) >> 5;
    int lane = threadIdx.x & 31;
    if (warp >= SROWS) return;
    const float4* xr = (const float4*)(x + (size_t)warp * CD);
    float4 v[4];
    float s = 0.f, s2 = 0.f;
#pragma unroll
    for (int i = 0; i < 4; i++) {
        v[i] = xr[lane + 32 * i];
        s  += v[i].x + v[i].y + v[i].z + v[i].w;
        s2 += v[i].x * v[i].x + v[i].y * v[i].y + v[i].z * v[i].z + v[i].w * v[i].w;
    }
    s = warp_sum(s); s2 = warp_sum(s2);
    float m = s * (1.0f / CD);
    float var = s2 * (1.0f / CD) - m * m;
    float r = rsqrtf(var + LN_EPS);
    float4* o = (float4*)(out + (size_t)warp * CD);
    const float4* g4p = (const float4*)g;
    const float4* b4p = (const float4*)b;
    const float4* k4p = (const float4*)kb;
    float qdot = 0.f;
#pragma unroll
    for (int i = 0; i < 4; i++) {
        float4 g4 = g4p[lane + 32 * i];
        float4 b4 = b4p[lane + 32 * i];
        float4 ov;
        ov.x = (v[i].x - m) * r * g4.x + b4.x;
        ov.y = (v[i].y - m) * r * g4.y + b4.y;
        ov.z = (v[i].z - m) * r * g4.z + b4.z;
        ov.w = (v[i].w - m) * r * g4.w + b4.w;
        o[lane + 32 * i] = ov;
        if (kb) {
            float4 k4 = k4p[lane + 32 * i];
            qdot += ov.x * k4.x + ov.y * k4.y + ov.z * k4.z + ov.w * k4.w;
        }
    }
    if (kb) {
        qdot = warp_sum(qdot);
        if (lane == 0) g_qkb[warp] = qdot;
    }
}

// ---------------- pipelined tf32 GEMM (cp.async, 3 stages) -------------------
#define GP_STRIDE 36
#define GP_TILE   (128 * GP_STRIDE)
#define GP_TILE_B (GP_TILE * 4)
#define GP_SMEM   (3 * 2 * GP_TILE_B)   // 110592

template <int ACT>
__device__ __forceinline__ void gemm_core_pipe(
    const float* __restrict__ A, int lda,
    const float* __restrict__ W, int ldw,
    const float* __restrict__ bias,
    float* __restrict__ C, int ldc, int K, int m0, int n0,
    float* __restrict__ C2, int c2cols) {
    extern __shared__ float sm[];
    float* As = sm;
    float* Bs = sm + 3 * GP_TILE;
    const uint32_t sa = smem_u32(As);
    const uint32_t sb = smem_u32(Bs);

    const int tid = threadIdx.x;
    const int warp = tid >> 5;
    const int lane = tid & 31;
    const int gid = lane >> 2;
    const int tig = lane & 3;
    const int mbase = (warp >> 2) * 64;
    const int nbase = (warp & 3) * 32;

    const int cr = tid >> 3;           // 0..31
    const int cc4 = (tid & 7) * 4;

    float c[4][4][4];
#pragma unroll
    for (int mi = 0; mi < 4; mi++)
#pragma unroll
        for (int ni = 0; ni < 4; ni++)
#pragma unroll
            for (int r = 0; r < 4; r++) c[mi][ni][r] = 0.f;

    const int NT = K >> 5;

#define GP_ISSUE(KT, ST)                                                           \
    do {                                                                           \
        uint32_t a_s = sa + (ST) * GP_TILE_B;                                      \
        uint32_t b_s = sb + (ST) * GP_TILE_B;                                      \
        _Pragma("unroll")                                                          \
        for (int i = 0; i < 4; i++) {                                              \
            int r = cr + i * 32;                                                   \
            cpa16(a_s + (r * GP_STRIDE + cc4) * 4,                                 \
                  A + (size_t)(m0 + r) * lda + (KT) * 32 + cc4);                   \
            cpa16(b_s + (r * GP_STRIDE + cc4) * 4,                                 \
                  W + (size_t)(n0 + r) * ldw + (KT) * 32 + cc4);                   \
        }                                                                          \
        CPA_COMMIT();                                                              \
    } while (0)

    GP_ISSUE(0, 0);
    GP_ISSUE(1, 1);

#pragma unroll 1
    for (int kt = 0; kt < NT; kt++) {
        if (kt < NT - 1) CPA_WAIT1(); else CPA_WAIT0();
        __syncthreads();
        if (kt + 2 < NT) GP_ISSUE(kt + 2, (kt + 2) % 3);

        const float* At = As + (kt % 3) * GP_TILE;
        const float* Bt = Bs + (kt % 3) * GP_TILE;
#pragma unroll
        for (int ks = 0; ks < 4; ks++) {
            uint32_t a[4][4], bf[4][2];
            int kk = ks * 8 + tig;
#pragma unroll
            for (int mi = 0; mi < 4; mi++) {
                const float* ap = At + (mbase + mi * 16 + gid) * GP_STRIDE;
                a[mi][0] = f2tf(ap[kk]);
                a[mi][1] = f2tf(ap[8 * GP_STRIDE + kk]);
                a[mi][2] = f2tf(ap[kk + 4]);
                a[mi][3] = f2tf(ap[8 * GP_STRIDE + kk + 4]);
            }
#pragma unroll
            for (int ni = 0; ni < 4; ni++) {
                const float* bp = Bt + (nbase + ni * 8 + gid) * GP_STRIDE;
                bf[ni][0] = f2tf(bp[kk]);
                bf[ni][1] = f2tf(bp[kk + 4]);
            }
#pragma unroll
            for (int mi = 0; mi < 4; mi++)
#pragma unroll
                for (int ni = 0; ni < 4; ni++) mma_tf32(c[mi][ni], a[mi], bf[ni]);
        }
        __syncthreads();
    }
#undef GP_ISSUE

#pragma unroll
    for (int mi = 0; mi < 4; mi++) {
        int r0 = m0 + mbase + mi * 16 + gid;
#pragma unroll
        for (int ni = 0; ni < 4; ni++) {
            int col = n0 + nbase + ni * 8 + tig * 2;
            float bv0 = bias ? __ldg(bias + col) : 0.f;
            float bv1 = bias ? __ldg(bias + col + 1) : 0.f;
            float v00 = c[mi][ni][0] + bv0, v01 = c[mi][ni][1] + bv1;
            float v10 = c[mi][ni][2] + bv0, v11 = c[mi][ni][3] + bv1;
            if (ACT == 1) { v00 = geluf(v00); v01 = geluf(v01); v10 = geluf(v10); v11 = geluf(v11); }
            *(float2*)(C + (size_t)r0 * ldc + col)       = make_float2(v00, v01);
            *(float2*)(C + (size_t)(r0 + 8) * ldc + col) = make_float2(v10, v11);
            if (C2 && col < c2cols) {
                *(float2*)(C2 + (size_t)r0 * c2cols + col)       = make_float2(v00, v01);
                *(float2*)(C2 + (size_t)(r0 + 8) * c2cols + col) = make_float2(v10, v11);
            }
        }
    }
}

template <int ACT>
__global__ __launch_bounds__(256) void gemm_tf32(
    const float* __restrict__ A, int lda,
    const float* __restrict__ W, int ldw,
    const float* __restrict__ bias,
    float* __restrict__ C, int ldc, int K) {
    gemm_core_pipe<ACT>(A, lda, W, ldw, bias, C, ldc, K,
                        blockIdx.y * 128, blockIdx.x * 128, nullptr, 0);
}

// per-iteration merged GEMM: z=0 -> [updates|gi] = aw @ W_cat^T + b_cat,
//                            z=1 -> gh = slots @ w_hh^T + b_hh
__global__ __launch_bounds__(256) void iter_gemm_dual(
    const float* __restrict__ w_hh, const float* __restrict__ b_hh,
    float* __restrict__ out2) {
    if (blockIdx.z == 0) {
        gemm_core_pipe<0>(g_aw, 512, g_wcat, 512, g_bcat, g_cat, 2048, 512,
                          blockIdx.y * 128, blockIdx.x * 128, out2, 512);
    } else {
        if (blockIdx.x >= 12) return;
        gemm_core_pipe<0>(g_slots, 512, w_hh, 512, b_hh, g_gh, 1536, 512,
                          blockIdx.y * 128, blockIdx.x * 128, nullptr, 0);
    }
}

// ---------------- fused attention pass ---------------------------------------
// LN0: read raw inputs, compute per-token LN in-tile, persist to g_xln.
#define FA_QKS   0
#define FA_TILE  4096
#define FA_SMS   (4096 + 16384)
#define FA_WSS   (FA_SMS + 128)
#define FA_QKB   (FA_WSS + 64)
#define FA_LNG   (FA_QKB + 8)
#define FA_LNB   (FA_LNG + 512)
#define FA_FLOATS (FA_LNB + 512)
#define FA_SMEM  (FA_FLOATS * 4)        // 86816

template <bool LN0>
__global__ void __launch_bounds__(256, 2) fused_attn_kernel(
    const float* __restrict__ xsrc,
    const float* __restrict__ lng, const float* __restrict__ lnb) {
    extern __shared__ float sm[];
    float* qks  = sm + FA_QKS;
    float* tile = sm + FA_TILE;
    float* sms  = sm + FA_SMS;
    float* wss  = sm + FA_WSS;
    float* qkbs = sm + FA_QKB;
    float* lngs = sm + FA_LNG;
    float* lnbs = sm + FA_LNB;
    const uint32_t tile_u = smem_u32(tile);

    const int chunk = blockIdx.x;
    const int b     = blockIdx.y;
    const int tid   = threadIdx.x;
    const int warp  = tid >> 5;
    const int lane  = tid & 31;

    {
        const float4* src = (const float4*)(g_qk + (size_t)b * 4096);
        float4* dst = (float4*)qks;
        for (int f = tid; f < 1024; f += 256) dst[f] = src[f];
        if (tid < 8) qkbs[tid] = g_qkb[b * 8 + tid];
        if (LN0) {
            for (int f = tid; f < 128; f += 256) {
                ((float4*)lngs)[f] = ((const float4*)lng)[f];
                ((float4*)lnbs)[f] = ((const float4*)lnb)[f];
            }
        }
    }

    const size_t jbase = (size_t)(b * CN + chunk * 256) * CD;
#define FA_ISSUE(ST)                                                               \
    do {                                                                           \
        uint32_t dst = tile_u + ((ST) & 1) * (8192 * 4);                           \
        _Pragma("unroll")                                                          \
        for (int i = 0; i < 8; i++) {                                              \
            int idx = tid + i * 256;                                               \
            int r = idx >> 7, c4 = (idx & 127) * 4;                                \
            cpa16(dst + (r * 512 + c4) * 4, xsrc + jbase + (size_t)((ST) * 16 + r) * 512 + c4); \
        }                                                                          \
        CPA_COMMIT();                                                              \
    } while (0)

    FA_ISSUE(0);

    float accA[8], accB[8], accx0 = 0.f, accx1 = 0.f, ssw[8];
#pragma unroll
    for (int s = 0; s < 8; s++) { accA[s] = 0.f; accB[s] = 0.f; ssw[s] = 0.f; }
    const int d0 = tid, d1 = tid + 256;

#pragma unroll 1
    for (int st = 0; st < 16; st++) {
        __syncthreads();
        if (st + 1 < 16) { FA_ISSUE(st + 1); CPA_WAIT1(); }
        else             { CPA_WAIT0(); }
        __syncthreads();
        float* tc = tile + (st & 1) * 8192;

        // Phase A: (optional LN) + dots for this warp's 2 tokens
        {
            const int tok0 = warp * 2;
            float4* xr0 = (float4*)(tc + tok0 * 512);
            float4* xr1 = xr0 + 128;
            float4 X0[4], X1[4];
#pragma unroll
            for (int cc = 0; cc < 4; cc++) {
                X0[cc] = xr0[cc * 32 + lane];
                X1[cc] = xr1[cc * 32 + lane];
            }
            if (LN0) {
                float s0 = 0.f, ss0 = 0.f, s1 = 0.f, ss1 = 0.f;
#pragma unroll
                for (int cc = 0; cc < 4; cc++) {
                    s0  += X0[cc].x + X0[cc].y + X0[cc].z + X0[cc].w;
                    ss0 += X0[cc].x * X0[cc].x + X0[cc].y * X0[cc].y + X0[cc].z * X0[cc].z + X0[cc].w * X0[cc].w;
                    s1  += X1[cc].x + X1[cc].y + X1[cc].z + X1[cc].w;
                    ss1 += X1[cc].x * X1[cc].x + X1[cc].y * X1[cc].y + X1[cc].z * X1[cc].z + X1[cc].w * X1[cc].w;
                }
                s0 = warp_sum(s0); ss0 = warp_sum(ss0);
                s1 = warp_sum(s1); ss1 = warp_sum(ss1);
                float m0 = s0 * (1.0f / CD);
                float r0 = rsqrtf(ss0 * (1.0f / CD) - m0 * m0 + LN_EPS);
                float m1 = s1 * (1.0f / CD);
                float r1 = rsqrtf(ss1 * (1.0f / CD) - m1 * m1 + LN_EPS);
                float4* gx0 = (float4*)(g_xln + jbase + (size_t)(st * 16 + tok0) * 512);
                float4* gx1 = gx0 + 128;
#pragma unroll
                for (int cc = 0; cc < 4; cc++) {
                    float4 g4 = ((const float4*)lngs)[cc * 32 + lane];
                    float4 b4 = ((const float4*)lnbs)[cc * 32 + lane];
                    float4 n0, n1;
                    n0.x = (X0[cc].x - m0) * r0 * g4.x + b4.x;
                    n0.y = (X0[cc].y - m0) * r0 * g4.y + b4.y;
                    n0.z = (X0[cc].z - m0) * r0 * g4.z + b4.z;
                    n0.w = (X0[cc].w - m0) * r0 * g4.w + b4.w;
                    n1.x = (X1[cc].x - m1) * r1 * g4.x + b4.x;
                    n1.y = (X1[cc].y - m1) * r1 * g4.y + b4.y;
                    n1.z = (X1[cc].z - m1) * r1 * g4.z + b4.z;
                    n1.w = (X1[cc].w - m1) * r1 * g4.w + b4.w;
                    X0[cc] = n0; X1[cc] = n1;
                    xr0[cc * 32 + lane] = n0;      // smem for Phase B
                    xr1[cc * 32 + lane] = n1;
                    gx0[cc * 32 + lane] = n0;      // persist for later iterations
                    gx1[cc * 32 + lane] = n1;
                }
            }
            float a0[8], a1[8];
#pragma unroll
            for (int s = 0; s < 8; s++) { a0[s] = 0.f; a1[s] = 0.f; }
#pragma unroll
            for (int cc = 0; cc < 4; cc++) {
#pragma unroll
                for (int s = 0; s < 8; s++) {
                    float4 q4 = ((const float4*)qks)[s * 128 + cc * 32 + lane];
                    a0[s] += X0[cc].x * q4.x + X0[cc].y * q4.y + X0[cc].z * q4.z + X0[cc].w * q4.w;
                    a1[s] += X1[cc].x * q4.x + X1[cc].y * q4.y + X1[cc].z * q4.z + X1[cc].w * q4.w;
                }
            }
#pragma unroll
            for (int o = 16; o; o >>= 1)
#pragma unroll
                for (int s = 0; s < 8; s++) {
                    a0[s] += __shfl_xor_sync(0xffffffffu, a0[s], o);
                    a1[s] += __shfl_xor_sync(0xffffffffu, a1[s], o);
                }
#pragma unroll
            for (int tk = 0; tk < 2; tk++) {
                float acc[8];
#pragma unroll
                for (int s = 0; s < 8; s++) acc[s] = (tk ? a1[s] : a0[s]) + qkbs[s];
                float mx = acc[0];
#pragma unroll
                for (int s = 1; s < 8; s++) mx = fmaxf(mx, acc[s]);
                float e[8], sum = 0.f;
#pragma unroll
                for (int s = 0; s < 8; s++) { e[s] = expf((acc[s] - mx) * ATT_SCALE); sum += e[s]; }
                float inv = 1.0f / sum;
#pragma unroll
                for (int s = 0; s < 8; s++) ssw[s] += e[s] * inv;
                float val = 0.f;
#pragma unroll
                for (int s = 0; s < 8; s++) if (lane == s) val = e[s] * inv;
                if (lane < 8) sms[(tok0 + tk) * 8 + lane] = val;
            }
        }
        __syncthreads();

        // Phase B
#pragma unroll
        for (int j = 0; j < 16; j++) {
            float4 s0 = *(const float4*)(sms + j * 8);
            float4 s1 = *(const float4*)(sms + j * 8 + 4);
            float x0 = tc[j * 512 + d0];
            float x1 = tc[j * 512 + d1];
            accA[0] += s0.x * x0; accB[0] += s0.x * x1;
            accA[1] += s0.y * x0; accB[1] += s0.y * x1;
            accA[2] += s0.z * x0; accB[2] += s0.z * x1;
            accA[3] += s0.w * x0; accB[3] += s0.w * x1;
            accA[4] += s1.x * x0; accB[4] += s1.x * x1;
            accA[5] += s1.y * x0; accB[5] += s1.y * x1;
            accA[6] += s1.z * x0; accB[6] += s1.z * x1;
            accA[7] += s1.w * x0; accB[7] += s1.w * x1;
            accx0 += x0; accx1 += x1;
        }
    }
#undef FA_ISSUE

#pragma unroll
    for (int s = 0; s < 8; s++) {
        size_t row = (size_t)(chunk * 256 + b * 8 + s) * 512;
        g_paw[row + d0] = accA[s];
        g_paw[row + d1] = accB[s];
    }
    g_pxsum[(size_t)(chunk * 32 + b) * 512 + d0] = accx0;
    g_pxsum[(size_t)(chunk * 32 + b) * 512 + d1] = accx1;
    if (lane == 0) {
#pragma unroll
        for (int s = 0; s < 8; s++) wss[warp * 8 + s] = ssw[s];
    }
    __syncthreads();
    if (tid < 8) {
        float t = 0.f;
#pragma unroll
        for (int w = 0; w < 8; w++) t += wss[w * 8 + tid];
        g_pssum[chunk * 256 + b * 8 + tid] = t;
    }
}

__global__ void aw_compose_kernel() {
    int idx = blockIdx.x * 256 + threadIdx.x;
    int row = idx >> 9;
    int d = idx & 511;
    int b = row >> 3;
    float den = 0.f, tot = 0.f, xs = 0.f;
#pragma unroll
    for (int c = 0; c < 8; c++) {
        den += g_pssum[c * 256 + row];
        tot += g_paw[(size_t)c * 131072 + (size_t)row * 512 + d];
        xs  += g_pxsum[(size_t)c * 16384 + (size_t)b * 512 + d];
    }
    float inv = 1.0f / (den + (float)CN * EPS_A);
    g_aw[idx] = (tot + EPS_A * xs) * inv;
}

__global__ void gru_elem_kernel() {
    int idx = blockIdx.x * 256 + threadIdx.x;
    int r = idx >> 9, d = idx & 511;
    const float* cr = g_cat + (size_t)r * 2048;
    float u   = cr[d];
    float i_r = cr[512 + d], i_z = cr[1024 + d], i_n = cr[1536 + d];
    const float* ghr = g_gh + (size_t)r * 1536;
    float h_r = ghr[d], h_z = ghr[d + 512], h_n = ghr[d + 1024];
    float rg = sigm(i_r + h_r);
    float z  = sigm(i_z + h_z);
    float nn = tanhf(i_n + rg * h_n);
    float h  = g_slots[idx];
    float h_new = (1.0f - z) * nn + z * h;
    g_slots[idx] = u + h_new;
}

// ---------------- launcher --------------------------------------------------
#define SYM(p, s) do { void* _v = nullptr; cudaGetSymbolAddress(&_v, s); (p) = (float*)_v; } while (0)

extern "C" void kernel_launch(void* const* d_in, const int* in_sizes, int n_in,
                              void* d_out, int out_size) {
    (void)in_sizes; (void)n_in; (void)out_size;
    const float* inputs         = (const float*)d_in[0];
    const float* slot_noise     = (const float*)d_in[1];
    const float* slots_mu       = (const float*)d_in[2];
    const float* slots_logsigma = (const float*)d_in[3];
    const float* k_w  = (const float*)d_in[4];
    const float* k_b  = (const float*)d_in[5];
    const float* v_w  = (const float*)d_in[6];
    const float* v_b  = (const float*)d_in[7];
    const float* gru_w_ih = (const float*)d_in[8];
    const float* gru_w_hh = (const float*)d_in[9];
    const float* gru_b_ih = (const float*)d_in[10];
    const float* gru_b_hh = (const float*)d_in[11];
    const float* ln_in_g = (const float*)d_in[12];
    const float* ln_in_b = (const float*)d_in[13];
    const float* ln_slots_g = (const float*)d_in[14];
    const float* ln_slots_b = (const float*)d_in[15];
    const float* ln_pre_g = (const float*)d_in[16];
    const float* ln_pre_b = (const float*)d_in[17];
    const float* mlp1_w = (const float*)d_in[18];
    const float* mlp1_b = (const float*)d_in[19];
    const float* mlp2_w = (const float*)d_in[20];
    const float* mlp2_b = (const float*)d_in[21];
    const float* mlp3_w = (const float*)d_in[22];
    const float* mlp3_b = (const float*)d_in[23];
    const float* mlp4_w = (const float*)d_in[24];
    const float* mlp4_b = (const float*)d_in[25];
    float* out = (float*)d_out;

    float *p_slots, *p_q, *p_qk, *p_kwT, *p_vwT, *p_wcat, *p_xln;
    float *p_s0, *p_h1, *p_h2, *p_h3;
    SYM(p_slots, g_slots); SYM(p_q, g_q); SYM(p_qk, g_qk);
    SYM(p_kwT, g_kwT); SYM(p_vwT, g_vwT); SYM(p_wcat, g_wcat); SYM(p_xln, g_xln);
    SYM(p_s0, g_s0); SYM(p_h1, g_h1); SYM(p_h2, g_h2); SYM(p_h3, g_h3);

    cudaFuncSetAttribute(fused_attn_kernel<true>,  cudaFuncAttributeMaxDynamicSharedMemorySize, FA_SMEM);
    cudaFuncSetAttribute(fused_attn_kernel<false>, cudaFuncAttributeMaxDynamicSharedMemorySize, FA_SMEM);
    cudaFuncSetAttribute(gemm_tf32<0>, cudaFuncAttributeMaxDynamicSharedMemorySize, GP_SMEM);
    cudaFuncSetAttribute(gemm_tf32<1>, cudaFuncAttributeMaxDynamicSharedMemorySize, GP_SMEM);
    cudaFuncSetAttribute(iter_gemm_dual, cudaFuncAttributeMaxDynamicSharedMemorySize, GP_SMEM);

    // prologue
    slot_init_kernel<<<512, 256>>>(slot_noise, slots_mu, slots_logsigma);
    transpose512_kernel<<<dim3(16, 16), dim3(32, 8)>>>(k_w, p_kwT);
    transpose512_kernel<<<dim3(16, 16), dim3(32, 8)>>>(v_w, p_vwT);
    copy_vw_kernel<<<1024, 256>>>(v_w, v_b);
    // W_cat rows 512..2047 = w_ih @ v_w
    gemm_tf32<0><<<dim3(4, 12), 256, GP_SMEM>>>(gru_w_ih, 512, p_vwT, 512, nullptr,
                                                p_wcat + 262144, 512, 512);
    bc_kernel<<<192, 256>>>(gru_w_ih, v_b, gru_b_ih);

    for (int it = 0; it < 3; it++) {
        ln_q_kernel<<<32, 256>>>(p_slots, ln_slots_g, ln_slots_b, p_q, k_b);
        gemm_tf32<0><<<dim3(4, 2), 256, GP_SMEM>>>(p_q, 512, p_kwT, 512, nullptr, p_qk, 512, 512);
        if (it == 0)
            fused_attn_kernel<true><<<dim3(8, 32), 256, FA_SMEM>>>(inputs, ln_in_g, ln_in_b);
        else
            fused_attn_kernel<false><<<dim3(8, 32), 256, FA_SMEM>>>(p_xln, nullptr, nullptr);
        aw_compose_kernel<<<512, 256>>>();
        iter_gemm_dual<<<dim3(16, 2, 2), 256, GP_SMEM>>>(gru_w_hh, gru_b_hh,
                                                         (it == 2) ? out : nullptr);
        gru_elem_kernel<<<512, 256>>>();
    }

    ln_q_kernel<<<32, 256>>>(p_slots, ln_pre_g, ln_pre_b, p_s0, nullptr);
    gemm_tf32<1><<<dim3(8, 2), 256, GP_SMEM>>>(p_s0, 512, mlp1_w, 512, mlp1_b, p_h1, 1024, 512);
    gemm_tf32<1><<<dim3(8, 2), 256, GP_SMEM>>>(p_h1, 1024, mlp2_w, 1024, mlp2_b, p_h2, 1024, 1024);
    gemm_tf32<1><<<dim3(4, 2), 256, GP_SMEM>>>(p_h2, 1024, mlp3_w, 1024, mlp3_b, p_h3, 512, 1024);
    gemm_tf32<0><<<dim3(2, 2), 256, GP_SMEM>>>(p_h3, 512, mlp4_w, 512, mlp4_b, out + 131072, 256, 512);
}